// round 9
// baseline (speedup 1.0000x reference)
#include <cuda_runtime.h>
#include <cuda_fp16.h>
#include <cstdint>
#include <cstddef>

#define N_NODES 8192
#define N_EDGES 65536
#define CACHE_E 16
#define MAXDEG 256

// ================= scratch (device globals) =================
__device__ float g_P[(size_t)N_NODES * 2048];    // [P1 | P3]
__device__ float g_Q[(size_t)N_NODES * 1200];    // [Q1 | Q2]

// CSR by dst
__device__ int g_cnt[N_NODES];
__device__ int g_off[N_NODES];
__device__ int g_fill[N_NODES];
__device__ int g_eid[N_EDGES];

// fp16 operands
__device__ __half g_nf_h[(size_t)N_NODES * 1024];
__device__ __half g_w2v_h[(size_t)N_NODES * 320];
__device__ __half g_zf_h[(size_t)N_NODES * 1024];
__device__ __half g_zfl_h[(size_t)N_NODES * 320];
__device__ __half g_WeT_h[(size_t)2048 * 1024];
__device__ __half g_WnT_h[(size_t)2048 * 1024];
__device__ __half g_WelT_h[(size_t)1280 * 320];
__device__ __half g_WnlT_h[(size_t)768 * 320];

// ================= small helpers =================
__device__ __forceinline__ uint32_t smem_u32(const void* p) {
    uint32_t a;
    asm("{ .reg .u64 t; cvta.to.shared.u64 t, %1; cvt.u32.u64 %0, t; }" : "=r"(a) : "l"(p));
    return a;
}
__device__ __forceinline__ void cp16(uint32_t dst, const void* src) {
    asm volatile("cp.async.cg.shared.global [%0], [%1], 16;" :: "r"(dst), "l"(src) : "memory");
}
__device__ __forceinline__ void cp_commit() {
    asm volatile("cp.async.commit_group;" ::: "memory");
}
__device__ __forceinline__ void ldmx4(uint32_t* r, uint32_t addr) {
    asm volatile("ldmatrix.sync.aligned.m8n8.x4.shared.b16 {%0,%1,%2,%3}, [%4];"
                 : "=r"(r[0]), "=r"(r[1]), "=r"(r[2]), "=r"(r[3]) : "r"(addr));
}
__device__ __forceinline__ void mma_f16(float* c, const uint32_t* a, const uint32_t* b) {
    asm volatile(
        "mma.sync.aligned.m16n8k16.row.col.f32.f16.f16.f32 "
        "{%0,%1,%2,%3}, {%4,%5,%6,%7}, {%8,%9}, {%0,%1,%2,%3};"
        : "+f"(c[0]), "+f"(c[1]), "+f"(c[2]), "+f"(c[3])
        : "r"(a[0]), "r"(a[1]), "r"(a[2]), "r"(a[3]), "r"(b[0]), "r"(b[1]));
}

// ================= plain fp16 HMMA GEMM (unchanged, known-good) =================
#define KC 64
#define TILE_B 16384
#define STAGE_B (2 * TILE_B)
#define GEMM_SMEM (2 * STAGE_B)

__device__ __forceinline__ void issue_chunk(
    uint32_t sb_stage,
    const __half* A, const __half* B,
    int ldA, int ldB, int rowBase, int colBase, int k0, int tid)
{
#pragma unroll
    for (int t = 0; t < 2; ++t) {
        const __half* src = (t == 0) ? A : B;
        const int row0 = (t == 0) ? rowBase : colBase;
        const int ld = (t == 0) ? ldA : ldB;
        const uint32_t tb = sb_stage + t * TILE_B;
#pragma unroll
        for (int i = 0; i < 4; ++i) {
            int idx = i * 256 + tid;
            int r = idx >> 3;
            int cch = idx & 7;
            uint32_t dst = tb + r * 128 + (((cch ^ (r & 7))) << 4);
            cp16(dst, src + (size_t)(row0 + r) * ld + k0 + cch * 8);
        }
    }
}

__global__ __launch_bounds__(256, 2) void mma_gemm(
    float* __restrict__ C, int ldc, int Nvalid,
    const __half* __restrict__ A1, const __half* __restrict__ B1, int K1,
    const __half* __restrict__ A2, const __half* __restrict__ B2, int K2,
    const float* __restrict__ bias, int do_relu)
{
    extern __shared__ char smem[];
    const uint32_t sb = smem_u32(smem);
    const int tid = threadIdx.x;
    const int wid = tid >> 5;
    const int lane = tid & 31;
    const int warp_m = wid & 3;
    const int warp_n = wid >> 2;
    const int rowBase = blockIdx.y * 128;
    const int colBase = blockIdx.x * 128;

    float c[2][8][4];
#pragma unroll
    for (int i = 0; i < 2; ++i)
#pragma unroll
        for (int j = 0; j < 8; ++j)
#pragma unroll
            for (int k = 0; k < 4; ++k) c[i][j][k] = 0.f;

    const int NC1 = K1 / KC;
    const int NC2 = K2 / KC;
    const int NC = NC1 + NC2;

    issue_chunk(sb, A1, B1, K1, K1, rowBase, colBase, 0, tid);
    cp_commit();

#pragma unroll 1
    for (int ch = 0; ch < NC; ++ch) {
        const uint32_t cur = sb + (uint32_t)(ch & 1) * STAGE_B;
        if (ch + 1 < NC) {
            int nc = ch + 1;
            if (nc < NC1)
                issue_chunk(sb + (uint32_t)(nc & 1) * STAGE_B, A1, B1,
                            K1, K1, rowBase, colBase, nc * KC, tid);
            else
                issue_chunk(sb + (uint32_t)(nc & 1) * STAGE_B, A2, B2,
                            K2, K2, rowBase, colBase, (nc - NC1) * KC, tid);
            cp_commit();
            asm volatile("cp.async.wait_group 1;" ::: "memory");
        } else {
            asm volatile("cp.async.wait_group 0;" ::: "memory");
        }
        __syncthreads();

#pragma unroll
        for (int ks = 0; ks < 4; ++ks) {
            uint32_t ah[2][4], bh[4][4];
#pragma unroll
            for (int mf = 0; mf < 2; ++mf) {
                int row = warp_m * 32 + mf * 16 + ((lane >> 3) & 1) * 8 + (lane & 7);
                int chunk = ks * 2 + (lane >> 4);
                uint32_t ad = cur + row * 128 + ((chunk ^ (row & 7)) << 4);
                ldmx4(ah[mf], ad);
            }
#pragma unroll
            for (int nf2 = 0; nf2 < 4; ++nf2) {
                int row = warp_n * 64 + nf2 * 16 + (lane >> 4) * 8 + (lane & 7);
                int chunk = ks * 2 + ((lane >> 3) & 1);
                uint32_t bd = cur + TILE_B + row * 128 + ((chunk ^ (row & 7)) << 4);
                ldmx4(bh[nf2], bd);
            }
#pragma unroll
            for (int mf = 0; mf < 2; ++mf)
#pragma unroll
                for (int nf = 0; nf < 8; ++nf)
                    mma_f16(c[mf][nf], ah[mf], &bh[nf >> 1][(nf & 1) * 2]);
        }
        __syncthreads();
    }

    const int r0 = rowBase + warp_m * 32 + (lane >> 2);
    const int colb = colBase + warp_n * 64 + (lane & 3) * 2;
#pragma unroll
    for (int mf = 0; mf < 2; ++mf) {
        int row = r0 + mf * 16;
#pragma unroll
        for (int nf = 0; nf < 8; ++nf) {
            int col = colb + nf * 8;
            if (col < Nvalid) {
                float b0 = 0.f, b1 = 0.f;
                if (bias) { b0 = bias[col]; b1 = bias[col + 1]; }
                float2 v0, v1;
                v0.x = c[mf][nf][0] + b0; v0.y = c[mf][nf][1] + b1;
                v1.x = c[mf][nf][2] + b0; v1.y = c[mf][nf][3] + b1;
                if (do_relu) {
                    v0.x = fmaxf(v0.x, 0.f); v0.y = fmaxf(v0.y, 0.f);
                    v1.x = fmaxf(v1.x, 0.f); v1.y = fmaxf(v1.y, 0.f);
                }
                *(float2*)(C + (size_t)row * ldc + col) = v0;
                *(float2*)(C + (size_t)(row + 8) * ldc + col) = v1;
            }
        }
    }
}

// ================= conversion kernels =================
__global__ void round_rows(const float* __restrict__ src, int M, int Ks, int Kd,
                           __half* __restrict__ hi) {
    size_t total = (size_t)M * Kd;
    size_t stride = (size_t)gridDim.x * blockDim.x;
    for (size_t i = (size_t)blockIdx.x * blockDim.x + threadIdx.x; i < total; i += stride) {
        int row = (int)(i / Kd);
        int col = (int)(i % Kd);
        float v = (col < Ks) ? src[(size_t)row * Ks + col] : 0.f;
        hi[i] = __float2half_rn(v);
    }
}

__global__ void transpose_round(const float* __restrict__ W, int ldw, int K, int N,
                                __half* __restrict__ hi, int Kd, int n0) {
    __shared__ float tile[32][33];
    int kb = blockIdx.y * 32, nb = blockIdx.x * 32;
#pragma unroll
    for (int i = 0; i < 4; ++i) {
        int k = kb + threadIdx.y + i * 8;
        int n = nb + threadIdx.x;
        tile[threadIdx.y + i * 8][threadIdx.x] = (k < K && n < N) ? W[(size_t)k * ldw + n] : 0.f;
    }
    __syncthreads();
#pragma unroll
    for (int i = 0; i < 4; ++i) {
        int n = nb + threadIdx.y + i * 8;
        int k = kb + threadIdx.x;
        if (n < N && k < Kd)
            hi[(size_t)(n0 + n) * Kd + k] = __float2half_rn(tile[threadIdx.x][threadIdx.y + i * 8]);
    }
}

// ================= CSR construction =================
__global__ void zero_cnt_kernel() {
    int i = blockIdx.x * blockDim.x + threadIdx.x;
    if (i < N_NODES) g_cnt[i] = 0;
}
__global__ void hist_kernel(const int* __restrict__ dst) {
    int e = blockIdx.x * blockDim.x + threadIdx.x;
    if (e < N_EDGES) atomicAdd(&g_cnt[dst[e]], 1);
}
__global__ __launch_bounds__(1024) void scan_kernel() {
    __shared__ int sm[1024];
    int t = threadIdx.x;
    int loc[8];
    int s = 0;
#pragma unroll
    for (int i = 0; i < 8; ++i) { loc[i] = g_cnt[t * 8 + i]; s += loc[i]; }
    sm[t] = s;
    __syncthreads();
    for (int off = 1; off < 1024; off <<= 1) {
        int v = sm[t];
        if (t >= off) v += sm[t - off];
        __syncthreads();
        sm[t] = v;
        __syncthreads();
    }
    int run = (t == 0) ? 0 : sm[t - 1];
#pragma unroll
    for (int i = 0; i < 8; ++i) {
        g_off[t * 8 + i] = run;
        g_fill[t * 8 + i] = run;
        run += loc[i];
    }
}
__global__ void fill_kernel(const int* __restrict__ dst) {
    int e = blockIdx.x * blockDim.x + threadIdx.x;
    if (e < N_EDGES) {
        int pos = atomicAdd(&g_fill[dst[e]], 1);
        g_eid[pos] = e;
    }
}

// ================= merged score+softmax+combine kernel (block per dst node) =================
__global__ __launch_bounds__(256, 3) void combine_all(
    const float* __restrict__ n_f, const float* __restrict__ w2v,
    const float* __restrict__ s_f, const int* __restrict__ src,
    const float* __restrict__ We, const float* __restrict__ be,
    const float* __restrict__ Wa,
    const float* __restrict__ bel, const float* __restrict__ Wal)
{
    extern __shared__ __half efc[];   // CACHE_E * 1024 halves (32 KB)
    const int d = blockIdx.x;
    const int t = threadIdx.x;
    const int lane = t & 31;
    const int deg = g_cnt[d];
    const int start = g_off[d];

    __shared__ int sm_eid[MAXDEG], sm_src[MAXDEG];
    __shared__ float sm_af[MAXDEG], sm_afl[MAXDEG];
    __shared__ float sm_scal[4];

    // prefetch edge list + src indices (breaks the per-edge pointer chase)
    for (int i = t; i < deg; i += 256) {
        int e = g_eid[start + i];
        sm_eid[i] = e;
        sm_src[i] = src[e];
    }
    for (int i = t; i < MAXDEG; i += 256) { sm_af[i] = 0.f; sm_afl[i] = 0.f; }
    __syncthreads();

    const float4* gP4 = (const float4*)g_P;
    const float4* gQ4 = (const float4*)g_Q;
    const float4* Ws4 = (const float4*)(We + (size_t)1024 * 1024);

    float4 wsr[16];
#pragma unroll
    for (int k = 0; k < 16; ++k) wsr[k] = Ws4[k * 256 + t];
    float4 p3r = gP4[(size_t)d * 512 + 256 + t];
    {
        float4 ber = ((const float4*)be)[t];
        p3r.x += ber.x; p3r.y += ber.y; p3r.z += ber.z; p3r.w += ber.w;
    }
    float4 war = ((const float4*)Wa)[t];
    float4 q2r = make_float4(0.f, 0.f, 0.f, 0.f);
    float4 walr = make_float4(0.f, 0.f, 0.f, 0.f);
    if (t < 150) {
        q2r = gQ4[(size_t)d * 300 + 150 + t];
        float4 belr = ((const float4*)bel)[t];
        q2r.x += belr.x; q2r.y += belr.y; q2r.z += belr.z; q2r.w += belr.w;
        walr = ((const float4*)Wal)[t];
    }

    // ---------- Phase A: e_f + scores ----------
#pragma unroll 1
    for (int i = 0; i < deg; ++i) {
        const int eid = sm_eid[i];
        const int s = sm_src[i];

        float4 v = gP4[(size_t)s * 512 + t];
        v.x += p3r.x; v.y += p3r.y; v.z += p3r.z; v.w += p3r.w;
#pragma unroll
        for (int k = 0; k < 16; ++k) {
            float sv = __ldg(&s_f[(size_t)eid * 16 + k]);
            v.x = fmaf(sv, wsr[k].x, v.x); v.y = fmaf(sv, wsr[k].y, v.y);
            v.z = fmaf(sv, wsr[k].z, v.z); v.w = fmaf(sv, wsr[k].w, v.w);
        }
        v.x = fmaxf(v.x, 0.f); v.y = fmaxf(v.y, 0.f);
        v.z = fmaxf(v.z, 0.f); v.w = fmaxf(v.w, 0.f);
        if (i < CACHE_E) {
            __half2 h0 = __floats2half2_rn(v.x, v.y);
            __half2 h1 = __floats2half2_rn(v.z, v.w);
            uint2 pk;
            pk.x = *(uint32_t*)&h0;
            pk.y = *(uint32_t*)&h1;
            *(uint2*)(efc + i * 1024 + 4 * t) = pk;
        }

        float acc = v.x * war.x + v.y * war.y + v.z * war.z + v.w * war.w;

        float accl = 0.f;
        if (t < 150) {
            float4 u = gQ4[(size_t)s * 300 + t];
            u.x += q2r.x; u.y += q2r.y; u.z += q2r.z; u.w += q2r.w;
            u.x = fmaxf(u.x, 0.f); u.y = fmaxf(u.y, 0.f);
            u.z = fmaxf(u.z, 0.f); u.w = fmaxf(u.w, 0.f);
            accl = u.x * walr.x + u.y * walr.y + u.z * walr.z + u.w * walr.w;
        }

#pragma unroll
        for (int off = 16; off > 0; off >>= 1) {
            acc += __shfl_down_sync(0xffffffffu, acc, off);
            accl += __shfl_down_sync(0xffffffffu, accl, off);
        }
        if (lane == 0) {
            atomicAdd(&sm_af[i], acc);
            if (accl != 0.f) atomicAdd(&sm_afl[i], accl);
        }
    }
    __syncthreads();

    // ---------- softmax scalars (warp 0) ----------
    if (t < 32) {
        float m = -1e30f, ml = -1e30f;
        for (int i = t; i < deg; i += 32) {
            m = fmaxf(m, sm_af[i]);
            ml = fmaxf(ml, sm_afl[i]);
        }
#pragma unroll
        for (int off = 16; off > 0; off >>= 1) {
            m = fmaxf(m, __shfl_xor_sync(0xffffffffu, m, off));
            ml = fmaxf(ml, __shfl_xor_sync(0xffffffffu, ml, off));
        }
        float den = 0.f, denl = 0.f;
        for (int i = t; i < deg; i += 32) {
            den += expf(sm_af[i] - m);
            denl += expf(sm_afl[i] - ml);
        }
#pragma unroll
        for (int off = 16; off > 0; off >>= 1) {
            den += __shfl_xor_sync(0xffffffffu, den, off);
            denl += __shfl_xor_sync(0xffffffffu, denl, off);
        }
        if (t == 0) {
            sm_scal[0] = m;
            sm_scal[1] = (deg > 0) ? 1.f / den : 0.f;
            sm_scal[2] = ml;
            sm_scal[3] = (deg > 0) ? 1.f / denl : 0.f;
        }
    }
    __syncthreads();

    {
        const float m = sm_scal[0], rden = sm_scal[1];
        const float ml = sm_scal[2], rdenl = sm_scal[3];
        for (int i = t; i < deg; i += 256) {
            sm_af[i] = expf(sm_af[i] - m) * rden;
            sm_afl[i] = expf(sm_afl[i] - ml) * rdenl;
        }
    }
    __syncthreads();

    // ---------- Phase B: weighted accumulate (fp16 gathers) ----------
    float4 acc = make_float4(0.f, 0.f, 0.f, 0.f);
    float4 accl = make_float4(0.f, 0.f, 0.f, 0.f);

#pragma unroll 1
    for (int i = 0; i < deg; ++i) {
        const int s = sm_src[i];
        const float alpha = sm_af[i];
        const float alphal = sm_afl[i];

        float4 v;
        if (i < CACHE_E) {
            uint2 pk = *(const uint2*)(efc + i * 1024 + 4 * t);
            __half2 h0 = *(__half2*)&pk.x;
            __half2 h1 = *(__half2*)&pk.y;
            float2 f0 = __half22float2(h0);
            float2 f1 = __half22float2(h1);
            v = make_float4(f0.x, f0.y, f1.x, f1.y);
        } else {
            const int eid = sm_eid[i];
            v = gP4[(size_t)s * 512 + t];
            v.x += p3r.x; v.y += p3r.y; v.z += p3r.z; v.w += p3r.w;
#pragma unroll
            for (int k = 0; k < 16; ++k) {
                float sv = __ldg(&s_f[(size_t)eid * 16 + k]);
                v.x = fmaf(sv, wsr[k].x, v.x); v.y = fmaf(sv, wsr[k].y, v.y);
                v.z = fmaf(sv, wsr[k].z, v.z); v.w = fmaf(sv, wsr[k].w, v.w);
            }
            v.x = fmaxf(v.x, 0.f); v.y = fmaxf(v.y, 0.f);
            v.z = fmaxf(v.z, 0.f); v.w = fmaxf(v.w, 0.f);
        }

        uint2 nraw = *(const uint2*)(g_nf_h + (size_t)s * 1024 + 4 * t);
        __half2 nh0 = *(__half2*)&nraw.x;
        __half2 nh1 = *(__half2*)&nraw.y;
        float2 n0 = __half22float2(nh0);
        float2 n1 = __half22float2(nh1);
        acc.x = fmaf(alpha, n0.x + v.x, acc.x);
        acc.y = fmaf(alpha, n0.y + v.y, acc.y);
        acc.z = fmaf(alpha, n1.x + v.z, acc.z);
        acc.w = fmaf(alpha, n1.y + v.w, acc.w);

        if (t < 75) {
            uint2 wraw = *(const uint2*)(g_w2v_h + (size_t)s * 320 + 4 * t);
            __half2 wh0 = *(__half2*)&wraw.x;
            __half2 wh1 = *(__half2*)&wraw.y;
            float2 w0 = __half22float2(wh0);
            float2 w1 = __half22float2(wh1);
            accl.x = fmaf(alphal, w0.x, accl.x);
            accl.y = fmaf(alphal, w0.y, accl.y);
            accl.z = fmaf(alphal, w1.x, accl.z);
            accl.w = fmaf(alphal, w1.y, accl.w);
        }
    }

    // ---------- write fp16 ----------
    {
        size_t o = (size_t)d * 1024 + 4 * t;
        g_zf_h[o + 0] = __float2half_rn(acc.x);
        g_zf_h[o + 1] = __float2half_rn(acc.y);
        g_zf_h[o + 2] = __float2half_rn(acc.z);
        g_zf_h[o + 3] = __float2half_rn(acc.w);
    }
    if (t < 75) {
        size_t o = (size_t)d * 320 + 4 * t;
        g_zfl_h[o + 0] = __float2half_rn(accl.x);
        g_zfl_h[o + 1] = __float2half_rn(accl.y);
        g_zfl_h[o + 2] = __float2half_rn(accl.z);
        g_zfl_h[o + 3] = __float2half_rn(accl.w);
    }
}

// ================= launch =================
extern "C" void kernel_launch(void* const* d_in, const int* in_sizes, int n_in,
                              void* d_out, int out_size) {
    const float* n_f  = (const float*)d_in[0];
    const float* w2v  = (const float*)d_in[1];
    const float* s_f  = (const float*)d_in[2];
    const int*   src  = (const int*)d_in[3];
    const int*   dst  = (const int*)d_in[4];
    const float* We   = (const float*)d_in[5];
    const float* be   = (const float*)d_in[6];
    const float* Wel  = (const float*)d_in[7];
    const float* bel  = (const float*)d_in[8];
    const float* Wa   = (const float*)d_in[9];
    const float* Wal  = (const float*)d_in[11];
    const float* Wn   = (const float*)d_in[13];
    const float* bn   = (const float*)d_in[14];
    const float* Wnl  = (const float*)d_in[15];
    const float* bnl  = (const float*)d_in[16];

    float* out      = (float*)d_out;
    float* out_lang = out + (size_t)N_NODES * 1024;

    float *P, *Q;
    __half *nf_h, *w2v_h, *zf_h, *zfl_h;
    __half *WeT_h, *WnT_h, *WelT_h, *WnlT_h;
    cudaGetSymbolAddress((void**)&P, g_P);
    cudaGetSymbolAddress((void**)&Q, g_Q);
    cudaGetSymbolAddress((void**)&nf_h, g_nf_h);
    cudaGetSymbolAddress((void**)&w2v_h, g_w2v_h);
    cudaGetSymbolAddress((void**)&zf_h, g_zf_h);
    cudaGetSymbolAddress((void**)&zfl_h, g_zfl_h);
    cudaGetSymbolAddress((void**)&WeT_h, g_WeT_h);
    cudaGetSymbolAddress((void**)&WnT_h, g_WnT_h);
    cudaGetSymbolAddress((void**)&WelT_h, g_WelT_h);
    cudaGetSymbolAddress((void**)&WnlT_h, g_WnlT_h);

    cudaFuncSetAttribute(mma_gemm, cudaFuncAttributeMaxDynamicSharedMemorySize, GEMM_SMEM);
    cudaFuncSetAttribute(combine_all, cudaFuncAttributeMaxDynamicSharedMemorySize,
                         CACHE_E * 1024 * sizeof(__half));

    dim3 tblk(32, 8);

    // conversions
    round_rows<<<2048, 256>>>(n_f, N_NODES, 1024, 1024, nf_h);
    round_rows<<<1024, 256>>>(w2v, N_NODES, 300, 320, w2v_h);
    transpose_round<<<dim3(32, 32), tblk>>>(We, 1024, 1024, 1024, WeT_h, 1024, 0);
    transpose_round<<<dim3(32, 32), tblk>>>(We + (size_t)1040 * 1024, 1024, 1024, 1024,
                                            WeT_h, 1024, 1024);
    transpose_round<<<dim3(19, 10), tblk>>>(Wel, 600, 300, 600, WelT_h, 320, 0);
    transpose_round<<<dim3(19, 10), tblk>>>(Wel + (size_t)300 * 600, 600, 300, 600,
                                            WelT_h, 320, 600);
    transpose_round<<<dim3(32, 32), tblk>>>(Wn, 1024, 1024, 1024, WnT_h, 1024, 0);
    transpose_round<<<dim3(32, 32), tblk>>>(Wn + (size_t)1024 * 1024, 1024, 1024, 1024,
                                            WnT_h, 1024, 1024);
    transpose_round<<<dim3(10, 10), tblk>>>(Wnl, 300, 300, 300, WnlT_h, 320, 0);
    transpose_round<<<dim3(10, 10), tblk>>>(Wnl + (size_t)300 * 300, 300, 300, 300,
                                            WnlT_h, 320, 300);

    // CSR
    zero_cnt_kernel<<<8, 1024>>>();
    hist_kernel<<<64, 1024>>>(dst);
    scan_kernel<<<1, 1024>>>();
    fill_kernel<<<64, 1024>>>(dst);

    // node projections
    mma_gemm<<<dim3(16, 64), 256, GEMM_SMEM>>>(P, 2048, 2048,
        nf_h, WeT_h, 1024, nullptr, nullptr, 0, nullptr, 0);
    mma_gemm<<<dim3(10, 64), 256, GEMM_SMEM>>>(Q, 1200, 1200,
        w2v_h, WelT_h, 320, nullptr, nullptr, 0, nullptr, 0);

    // merged edge scores + softmax + aggregate
    combine_all<<<N_NODES, 256, CACHE_E * 1024 * sizeof(__half)>>>(
        n_f, w2v, s_f, src, We, be, Wa, bel, Wal);

    // node apply
    mma_gemm<<<dim3(8, 64), 256, GEMM_SMEM>>>(out, 1024, 1024,
        nf_h, WnT_h, 1024,
        zf_h, WnT_h + (size_t)1024 * 1024, 1024,
        bn, 1);
    mma_gemm<<<dim3(3, 64), 256, GEMM_SMEM>>>(out_lang, 300, 300,
        w2v_h, WnlT_h, 320,
        zfl_h, WnlT_h + (size_t)300 * 320, 320,
        bnl, 1);
}

// round 10
// speedup vs baseline: 1.1086x; 1.1086x over previous
#include <cuda_runtime.h>
#include <cuda_fp16.h>
#include <cstdint>
#include <cstddef>

#define N_NODES 8192
#define N_EDGES 65536
#define CACHE_E 16
#define MAXDEG 256

// ================= scratch (device globals) =================
__device__ float g_P[(size_t)N_NODES * 2048];    // [P1 | P3]
__device__ float g_Q[(size_t)N_NODES * 1200];    // [Q1 | Q2]

// CSR by dst
__device__ int g_cnt[N_NODES];
__device__ int g_off[N_NODES];
__device__ int g_fill[N_NODES];
__device__ int g_eid[N_EDGES];

// fp16 operands
__device__ __half g_nf_h[(size_t)N_NODES * 1024];
__device__ __half g_w2v_h[(size_t)N_NODES * 320];
__device__ __half g_zf_h[(size_t)N_NODES * 1024];
__device__ __half g_zfl_h[(size_t)N_NODES * 320];
__device__ __half g_WeT_h[(size_t)2048 * 1024];
__device__ __half g_WnT_h[(size_t)2048 * 1024];
__device__ __half g_WelT_h[(size_t)1280 * 320];
__device__ __half g_WnlT_h[(size_t)768 * 320];

// ================= small helpers =================
__device__ __forceinline__ uint32_t smem_u32(const void* p) {
    uint32_t a;
    asm("{ .reg .u64 t; cvta.to.shared.u64 t, %1; cvt.u32.u64 %0, t; }" : "=r"(a) : "l"(p));
    return a;
}
__device__ __forceinline__ void cp16(uint32_t dst, const void* src) {
    asm volatile("cp.async.cg.shared.global [%0], [%1], 16;" :: "r"(dst), "l"(src) : "memory");
}
__device__ __forceinline__ void cp_commit() {
    asm volatile("cp.async.commit_group;" ::: "memory");
}
__device__ __forceinline__ void ldmx4(uint32_t* r, uint32_t addr) {
    asm volatile("ldmatrix.sync.aligned.m8n8.x4.shared.b16 {%0,%1,%2,%3}, [%4];"
                 : "=r"(r[0]), "=r"(r[1]), "=r"(r[2]), "=r"(r[3]) : "r"(addr));
}
__device__ __forceinline__ void mma_f16(float* c, const uint32_t* a, const uint32_t* b) {
    asm volatile(
        "mma.sync.aligned.m16n8k16.row.col.f32.f16.f16.f32 "
        "{%0,%1,%2,%3}, {%4,%5,%6,%7}, {%8,%9}, {%0,%1,%2,%3};"
        : "+f"(c[0]), "+f"(c[1]), "+f"(c[2]), "+f"(c[3])
        : "r"(a[0]), "r"(a[1]), "r"(a[2]), "r"(a[3]), "r"(b[0]), "r"(b[1]));
}

// ================= plain fp16 HMMA GEMM (unchanged, known-good) =================
#define KC 64
#define TILE_B 16384
#define STAGE_B (2 * TILE_B)
#define GEMM_SMEM (2 * STAGE_B)

__device__ __forceinline__ void issue_chunk(
    uint32_t sb_stage,
    const __half* A, const __half* B,
    int ldA, int ldB, int rowBase, int colBase, int k0, int tid)
{
#pragma unroll
    for (int t = 0; t < 2; ++t) {
        const __half* src = (t == 0) ? A : B;
        const int row0 = (t == 0) ? rowBase : colBase;
        const int ld = (t == 0) ? ldA : ldB;
        const uint32_t tb = sb_stage + t * TILE_B;
#pragma unroll
        for (int i = 0; i < 4; ++i) {
            int idx = i * 256 + tid;
            int r = idx >> 3;
            int cch = idx & 7;
            uint32_t dst = tb + r * 128 + (((cch ^ (r & 7))) << 4);
            cp16(dst, src + (size_t)(row0 + r) * ld + k0 + cch * 8);
        }
    }
}

__global__ __launch_bounds__(256, 2) void mma_gemm(
    float* __restrict__ C, int ldc, int Nvalid,
    const __half* __restrict__ A1, const __half* __restrict__ B1, int K1,
    const __half* __restrict__ A2, const __half* __restrict__ B2, int K2,
    const float* __restrict__ bias, int do_relu)
{
    extern __shared__ char smem[];
    const uint32_t sb = smem_u32(smem);
    const int tid = threadIdx.x;
    const int wid = tid >> 5;
    const int lane = tid & 31;
    const int warp_m = wid & 3;
    const int warp_n = wid >> 2;
    const int rowBase = blockIdx.y * 128;
    const int colBase = blockIdx.x * 128;

    float c[2][8][4];
#pragma unroll
    for (int i = 0; i < 2; ++i)
#pragma unroll
        for (int j = 0; j < 8; ++j)
#pragma unroll
            for (int k = 0; k < 4; ++k) c[i][j][k] = 0.f;

    const int NC1 = K1 / KC;
    const int NC2 = K2 / KC;
    const int NC = NC1 + NC2;

    issue_chunk(sb, A1, B1, K1, K1, rowBase, colBase, 0, tid);
    cp_commit();

#pragma unroll 1
    for (int ch = 0; ch < NC; ++ch) {
        const uint32_t cur = sb + (uint32_t)(ch & 1) * STAGE_B;
        if (ch + 1 < NC) {
            int nc = ch + 1;
            if (nc < NC1)
                issue_chunk(sb + (uint32_t)(nc & 1) * STAGE_B, A1, B1,
                            K1, K1, rowBase, colBase, nc * KC, tid);
            else
                issue_chunk(sb + (uint32_t)(nc & 1) * STAGE_B, A2, B2,
                            K2, K2, rowBase, colBase, (nc - NC1) * KC, tid);
            cp_commit();
            asm volatile("cp.async.wait_group 1;" ::: "memory");
        } else {
            asm volatile("cp.async.wait_group 0;" ::: "memory");
        }
        __syncthreads();

#pragma unroll
        for (int ks = 0; ks < 4; ++ks) {
            uint32_t ah[2][4], bh[4][4];
#pragma unroll
            for (int mf = 0; mf < 2; ++mf) {
                int row = warp_m * 32 + mf * 16 + ((lane >> 3) & 1) * 8 + (lane & 7);
                int chunk = ks * 2 + (lane >> 4);
                uint32_t ad = cur + row * 128 + ((chunk ^ (row & 7)) << 4);
                ldmx4(ah[mf], ad);
            }
#pragma unroll
            for (int nf2 = 0; nf2 < 4; ++nf2) {
                int row = warp_n * 64 + nf2 * 16 + (lane >> 4) * 8 + (lane & 7);
                int chunk = ks * 2 + ((lane >> 3) & 1);
                uint32_t bd = cur + TILE_B + row * 128 + ((chunk ^ (row & 7)) << 4);
                ldmx4(bh[nf2], bd);
            }
#pragma unroll
            for (int mf = 0; mf < 2; ++mf)
#pragma unroll
                for (int nf = 0; nf < 8; ++nf)
                    mma_f16(c[mf][nf], ah[mf], &bh[nf >> 1][(nf & 1) * 2]);
        }
        __syncthreads();
    }

    const int r0 = rowBase + warp_m * 32 + (lane >> 2);
    const int colb = colBase + warp_n * 64 + (lane & 3) * 2;
#pragma unroll
    for (int mf = 0; mf < 2; ++mf) {
        int row = r0 + mf * 16;
#pragma unroll
        for (int nf = 0; nf < 8; ++nf) {
            int col = colb + nf * 8;
            if (col < Nvalid) {
                float b0 = 0.f, b1 = 0.f;
                if (bias) { b0 = bias[col]; b1 = bias[col + 1]; }
                float2 v0, v1;
                v0.x = c[mf][nf][0] + b0; v0.y = c[mf][nf][1] + b1;
                v1.x = c[mf][nf][2] + b0; v1.y = c[mf][nf][3] + b1;
                if (do_relu) {
                    v0.x = fmaxf(v0.x, 0.f); v0.y = fmaxf(v0.y, 0.f);
                    v1.x = fmaxf(v1.x, 0.f); v1.y = fmaxf(v1.y, 0.f);
                }
                *(float2*)(C + (size_t)row * ldc + col) = v0;
                *(float2*)(C + (size_t)(row + 8) * ldc + col) = v1;
            }
        }
    }
}

// ================= conversion kernels =================
__global__ void round_rows(const float* __restrict__ src, int M, int Ks, int Kd,
                           __half* __restrict__ hi) {
    size_t total = (size_t)M * Kd;
    size_t stride = (size_t)gridDim.x * blockDim.x;
    for (size_t i = (size_t)blockIdx.x * blockDim.x + threadIdx.x; i < total; i += stride) {
        int row = (int)(i / Kd);
        int col = (int)(i % Kd);
        float v = (col < Ks) ? src[(size_t)row * Ks + col] : 0.f;
        hi[i] = __float2half_rn(v);
    }
}

__global__ void transpose_round(const float* __restrict__ W, int ldw, int K, int N,
                                __half* __restrict__ hi, int Kd, int n0) {
    __shared__ float tile[32][33];
    int kb = blockIdx.y * 32, nb = blockIdx.x * 32;
#pragma unroll
    for (int i = 0; i < 4; ++i) {
        int k = kb + threadIdx.y + i * 8;
        int n = nb + threadIdx.x;
        tile[threadIdx.y + i * 8][threadIdx.x] = (k < K && n < N) ? W[(size_t)k * ldw + n] : 0.f;
    }
    __syncthreads();
#pragma unroll
    for (int i = 0; i < 4; ++i) {
        int n = nb + threadIdx.y + i * 8;
        int k = kb + threadIdx.x;
        if (n < N && k < Kd)
            hi[(size_t)(n0 + n) * Kd + k] = __float2half_rn(tile[threadIdx.x][threadIdx.y + i * 8]);
    }
}

// ================= CSR construction =================
__global__ void zero_cnt_kernel() {
    int i = blockIdx.x * blockDim.x + threadIdx.x;
    if (i < N_NODES) g_cnt[i] = 0;
}
__global__ void hist_kernel(const int* __restrict__ dst) {
    int e = blockIdx.x * blockDim.x + threadIdx.x;
    if (e < N_EDGES) atomicAdd(&g_cnt[dst[e]], 1);
}
__global__ __launch_bounds__(1024) void scan_kernel() {
    __shared__ int sm[1024];
    int t = threadIdx.x;
    int loc[8];
    int s = 0;
#pragma unroll
    for (int i = 0; i < 8; ++i) { loc[i] = g_cnt[t * 8 + i]; s += loc[i]; }
    sm[t] = s;
    __syncthreads();
    for (int off = 1; off < 1024; off <<= 1) {
        int v = sm[t];
        if (t >= off) v += sm[t - off];
        __syncthreads();
        sm[t] = v;
        __syncthreads();
    }
    int run = (t == 0) ? 0 : sm[t - 1];
#pragma unroll
    for (int i = 0; i < 8; ++i) {
        g_off[t * 8 + i] = run;
        g_fill[t * 8 + i] = run;
        run += loc[i];
    }
}
__global__ void fill_kernel(const int* __restrict__ dst) {
    int e = blockIdx.x * blockDim.x + threadIdx.x;
    if (e < N_EDGES) {
        int pos = atomicAdd(&g_fill[dst[e]], 1);
        g_eid[pos] = e;
    }
}

// ================= merged score+softmax+combine kernel (block per dst node) =================
__global__ __launch_bounds__(256) void combine_all(
    const float* __restrict__ n_f, const float* __restrict__ w2v,
    const float* __restrict__ s_f, const int* __restrict__ src,
    const float* __restrict__ We, const float* __restrict__ be,
    const float* __restrict__ Wa,
    const float* __restrict__ bel, const float* __restrict__ Wal)
{
    extern __shared__ __half efc[];   // CACHE_E * 1024 halves (32 KB)
    const int d = blockIdx.x;
    const int t = threadIdx.x;
    const int lane = t & 31;
    const int deg = g_cnt[d];
    const int start = g_off[d];

    __shared__ int sm_eid[MAXDEG], sm_src[MAXDEG];
    __shared__ float sm_af[MAXDEG], sm_afl[MAXDEG];
    __shared__ float sm_scal[4];

    // prefetch edge list + src indices (breaks the per-edge pointer chase)
    for (int i = t; i < deg; i += 256) {
        int e = g_eid[start + i];
        sm_eid[i] = e;
        sm_src[i] = src[e];
    }
    for (int i = t; i < MAXDEG; i += 256) { sm_af[i] = 0.f; sm_afl[i] = 0.f; }
    __syncthreads();

    const float4* gP4 = (const float4*)g_P;
    const float4* gQ4 = (const float4*)g_Q;
    const float4* Ws4 = (const float4*)(We + (size_t)1024 * 1024);

    float4 wsr[16];
#pragma unroll
    for (int k = 0; k < 16; ++k) wsr[k] = Ws4[k * 256 + t];
    float4 p3r = gP4[(size_t)d * 512 + 256 + t];
    {
        float4 ber = ((const float4*)be)[t];
        p3r.x += ber.x; p3r.y += ber.y; p3r.z += ber.z; p3r.w += ber.w;
    }
    float4 war = ((const float4*)Wa)[t];
    float4 q2r = make_float4(0.f, 0.f, 0.f, 0.f);
    float4 walr = make_float4(0.f, 0.f, 0.f, 0.f);
    if (t < 150) {
        q2r = gQ4[(size_t)d * 300 + 150 + t];
        float4 belr = ((const float4*)bel)[t];
        q2r.x += belr.x; q2r.y += belr.y; q2r.z += belr.z; q2r.w += belr.w;
        walr = ((const float4*)Wal)[t];
    }

    // ---------- Phase A: e_f + scores ----------
#pragma unroll 1
    for (int i = 0; i < deg; ++i) {
        const int eid = sm_eid[i];
        const int s = sm_src[i];

        float4 v = gP4[(size_t)s * 512 + t];
        v.x += p3r.x; v.y += p3r.y; v.z += p3r.z; v.w += p3r.w;
#pragma unroll
        for (int k = 0; k < 16; ++k) {
            float sv = __ldg(&s_f[(size_t)eid * 16 + k]);
            v.x = fmaf(sv, wsr[k].x, v.x); v.y = fmaf(sv, wsr[k].y, v.y);
            v.z = fmaf(sv, wsr[k].z, v.z); v.w = fmaf(sv, wsr[k].w, v.w);
        }
        v.x = fmaxf(v.x, 0.f); v.y = fmaxf(v.y, 0.f);
        v.z = fmaxf(v.z, 0.f); v.w = fmaxf(v.w, 0.f);
        if (i < CACHE_E) {
            __half2 h0 = __floats2half2_rn(v.x, v.y);
            __half2 h1 = __floats2half2_rn(v.z, v.w);
            uint2 pk;
            pk.x = *(uint32_t*)&h0;
            pk.y = *(uint32_t*)&h1;
            *(uint2*)(efc + i * 1024 + 4 * t) = pk;
        }

        float acc = v.x * war.x + v.y * war.y + v.z * war.z + v.w * war.w;

        float accl = 0.f;
        if (t < 150) {
            float4 u = gQ4[(size_t)s * 300 + t];
            u.x += q2r.x; u.y += q2r.y; u.z += q2r.z; u.w += q2r.w;
            u.x = fmaxf(u.x, 0.f); u.y = fmaxf(u.y, 0.f);
            u.z = fmaxf(u.z, 0.f); u.w = fmaxf(u.w, 0.f);
            accl = u.x * walr.x + u.y * walr.y + u.z * walr.z + u.w * walr.w;
        }

#pragma unroll
        for (int off = 16; off > 0; off >>= 1) {
            acc += __shfl_down_sync(0xffffffffu, acc, off);
            accl += __shfl_down_sync(0xffffffffu, accl, off);
        }
        if (lane == 0) {
            atomicAdd(&sm_af[i], acc);
            if (accl != 0.f) atomicAdd(&sm_afl[i], accl);
        }
    }
    __syncthreads();

    // ---------- softmax scalars (warp 0) ----------
    if (t < 32) {
        float m = -1e30f, ml = -1e30f;
        for (int i = t; i < deg; i += 32) {
            m = fmaxf(m, sm_af[i]);
            ml = fmaxf(ml, sm_afl[i]);
        }
#pragma unroll
        for (int off = 16; off > 0; off >>= 1) {
            m = fmaxf(m, __shfl_xor_sync(0xffffffffu, m, off));
            ml = fmaxf(ml, __shfl_xor_sync(0xffffffffu, ml, off));
        }
        float den = 0.f, denl = 0.f;
        for (int i = t; i < deg; i += 32) {
            den += expf(sm_af[i] - m);
            denl += expf(sm_afl[i] - ml);
        }
#pragma unroll
        for (int off = 16; off > 0; off >>= 1) {
            den += __shfl_xor_sync(0xffffffffu, den, off);
            denl += __shfl_xor_sync(0xffffffffu, denl, off);
        }
        if (t == 0) {
            sm_scal[0] = m;
            sm_scal[1] = (deg > 0) ? 1.f / den : 0.f;
            sm_scal[2] = ml;
            sm_scal[3] = (deg > 0) ? 1.f / denl : 0.f;
        }
    }
    __syncthreads();

    {
        const float m = sm_scal[0], rden = sm_scal[1];
        const float ml = sm_scal[2], rdenl = sm_scal[3];
        for (int i = t; i < deg; i += 256) {
            sm_af[i] = expf(sm_af[i] - m) * rden;
            sm_afl[i] = expf(sm_afl[i] - ml) * rdenl;
        }
    }
    __syncthreads();

    // ---------- Phase B: weighted accumulate (fp16 gathers) ----------
    float4 acc = make_float4(0.f, 0.f, 0.f, 0.f);
    float4 accl = make_float4(0.f, 0.f, 0.f, 0.f);

#pragma unroll 1
    for (int i = 0; i < deg; ++i) {
        const int s = sm_src[i];
        const float alpha = sm_af[i];
        const float alphal = sm_afl[i];

        float4 v;
        if (i < CACHE_E) {
            uint2 pk = *(const uint2*)(efc + i * 1024 + 4 * t);
            __half2 h0 = *(__half2*)&pk.x;
            __half2 h1 = *(__half2*)&pk.y;
            float2 f0 = __half22float2(h0);
            float2 f1 = __half22float2(h1);
            v = make_float4(f0.x, f0.y, f1.x, f1.y);
        } else {
            const int eid = sm_eid[i];
            v = gP4[(size_t)s * 512 + t];
            v.x += p3r.x; v.y += p3r.y; v.z += p3r.z; v.w += p3r.w;
#pragma unroll
            for (int k = 0; k < 16; ++k) {
                float sv = __ldg(&s_f[(size_t)eid * 16 + k]);
                v.x = fmaf(sv, wsr[k].x, v.x); v.y = fmaf(sv, wsr[k].y, v.y);
                v.z = fmaf(sv, wsr[k].z, v.z); v.w = fmaf(sv, wsr[k].w, v.w);
            }
            v.x = fmaxf(v.x, 0.f); v.y = fmaxf(v.y, 0.f);
            v.z = fmaxf(v.z, 0.f); v.w = fmaxf(v.w, 0.f);
        }

        uint2 nraw = *(const uint2*)(g_nf_h + (size_t)s * 1024 + 4 * t);
        __half2 nh0 = *(__half2*)&nraw.x;
        __half2 nh1 = *(__half2*)&nraw.y;
        float2 n0 = __half22float2(nh0);
        float2 n1 = __half22float2(nh1);
        acc.x = fmaf(alpha, n0.x + v.x, acc.x);
        acc.y = fmaf(alpha, n0.y + v.y, acc.y);
        acc.z = fmaf(alpha, n1.x + v.z, acc.z);
        acc.w = fmaf(alpha, n1.y + v.w, acc.w);

        if (t < 75) {
            uint2 wraw = *(const uint2*)(g_w2v_h + (size_t)s * 320 + 4 * t);
            __half2 wh0 = *(__half2*)&wraw.x;
            __half2 wh1 = *(__half2*)&wraw.y;
            float2 w0 = __half22float2(wh0);
            float2 w1 = __half22float2(wh1);
            accl.x = fmaf(alphal, w0.x, accl.x);
            accl.y = fmaf(alphal, w0.y, accl.y);
            accl.z = fmaf(alphal, w1.x, accl.z);
            accl.w = fmaf(alphal, w1.y, accl.w);
        }
    }

    // ---------- write fp16 ----------
    {
        size_t o = (size_t)d * 1024 + 4 * t;
        g_zf_h[o + 0] = __float2half_rn(acc.x);
        g_zf_h[o + 1] = __float2half_rn(acc.y);
        g_zf_h[o + 2] = __float2half_rn(acc.z);
        g_zf_h[o + 3] = __float2half_rn(acc.w);
    }
    if (t < 75) {
        size_t o = (size_t)d * 320 + 4 * t;
        g_zfl_h[o + 0] = __float2half_rn(accl.x);
        g_zfl_h[o + 1] = __float2half_rn(accl.y);
        g_zfl_h[o + 2] = __float2half_rn(accl.z);
        g_zfl_h[o + 3] = __float2half_rn(accl.w);
    }
}

// ================= launch =================
extern "C" void kernel_launch(void* const* d_in, const int* in_sizes, int n_in,
                              void* d_out, int out_size) {
    const float* n_f  = (const float*)d_in[0];
    const float* w2v  = (const float*)d_in[1];
    const float* s_f  = (const float*)d_in[2];
    const int*   src  = (const int*)d_in[3];
    const int*   dst  = (const int*)d_in[4];
    const float* We   = (const float*)d_in[5];
    const float* be   = (const float*)d_in[6];
    const float* Wel  = (const float*)d_in[7];
    const float* bel  = (const float*)d_in[8];
    const float* Wa   = (const float*)d_in[9];
    const float* Wal  = (const float*)d_in[11];
    const float* Wn   = (const float*)d_in[13];
    const float* bn   = (const float*)d_in[14];
    const float* Wnl  = (const float*)d_in[15];
    const float* bnl  = (const float*)d_in[16];

    float* out      = (float*)d_out;
    float* out_lang = out + (size_t)N_NODES * 1024;

    float *P, *Q;
    __half *nf_h, *w2v_h, *zf_h, *zfl_h;
    __half *WeT_h, *WnT_h, *WelT_h, *WnlT_h;
    cudaGetSymbolAddress((void**)&P, g_P);
    cudaGetSymbolAddress((void**)&Q, g_Q);
    cudaGetSymbolAddress((void**)&nf_h, g_nf_h);
    cudaGetSymbolAddress((void**)&w2v_h, g_w2v_h);
    cudaGetSymbolAddress((void**)&zf_h, g_zf_h);
    cudaGetSymbolAddress((void**)&zfl_h, g_zfl_h);
    cudaGetSymbolAddress((void**)&WeT_h, g_WeT_h);
    cudaGetSymbolAddress((void**)&WnT_h, g_WnT_h);
    cudaGetSymbolAddress((void**)&WelT_h, g_WelT_h);
    cudaGetSymbolAddress((void**)&WnlT_h, g_WnlT_h);

    cudaFuncSetAttribute(mma_gemm, cudaFuncAttributeMaxDynamicSharedMemorySize, GEMM_SMEM);
    cudaFuncSetAttribute(combine_all, cudaFuncAttributeMaxDynamicSharedMemorySize,
                         CACHE_E * 1024 * sizeof(__half));

    dim3 tblk(32, 8);

    // conversions
    round_rows<<<2048, 256>>>(n_f, N_NODES, 1024, 1024, nf_h);
    round_rows<<<1024, 256>>>(w2v, N_NODES, 300, 320, w2v_h);
    transpose_round<<<dim3(32, 32), tblk>>>(We, 1024, 1024, 1024, WeT_h, 1024, 0);
    transpose_round<<<dim3(32, 32), tblk>>>(We + (size_t)1040 * 1024, 1024, 1024, 1024,
                                            WeT_h, 1024, 1024);
    transpose_round<<<dim3(19, 10), tblk>>>(Wel, 600, 300, 600, WelT_h, 320, 0);
    transpose_round<<<dim3(19, 10), tblk>>>(Wel + (size_t)300 * 600, 600, 300, 600,
                                            WelT_h, 320, 600);
    transpose_round<<<dim3(32, 32), tblk>>>(Wn, 1024, 1024, 1024, WnT_h, 1024, 0);
    transpose_round<<<dim3(32, 32), tblk>>>(Wn + (size_t)1024 * 1024, 1024, 1024, 1024,
                                            WnT_h, 1024, 1024);
    transpose_round<<<dim3(10, 10), tblk>>>(Wnl, 300, 300, 300, WnlT_h, 320, 0);
    transpose_round<<<dim3(10, 10), tblk>>>(Wnl + (size_t)300 * 300, 300, 300, 300,
                                            WnlT_h, 320, 300);

    // CSR
    zero_cnt_kernel<<<8, 1024>>>();
    hist_kernel<<<64, 1024>>>(dst);
    scan_kernel<<<1, 1024>>>();
    fill_kernel<<<64, 1024>>>(dst);

    // node projections
    mma_gemm<<<dim3(16, 64), 256, GEMM_SMEM>>>(P, 2048, 2048,
        nf_h, WeT_h, 1024, nullptr, nullptr, 0, nullptr, 0);
    mma_gemm<<<dim3(10, 64), 256, GEMM_SMEM>>>(Q, 1200, 1200,
        w2v_h, WelT_h, 320, nullptr, nullptr, 0, nullptr, 0);

    // merged edge scores + softmax + aggregate
    combine_all<<<N_NODES, 256, CACHE_E * 1024 * sizeof(__half)>>>(
        n_f, w2v, s_f, src, We, be, Wa, bel, Wal);

    // node apply
    mma_gemm<<<dim3(8, 64), 256, GEMM_SMEM>>>(out, 1024, 1024,
        nf_h, WnT_h, 1024,
        zf_h, WnT_h + (size_t)1024 * 1024, 1024,
        bn, 1);
    mma_gemm<<<dim3(3, 64), 256, GEMM_SMEM>>>(out_lang, 300, 300,
        w2v_h, WnlT_h, 320,
        zfl_h, WnlT_h + (size_t)300 * 320, 320,
        bnl, 1);
}

// round 11
// speedup vs baseline: 1.1296x; 1.0190x over previous
#include <cuda_runtime.h>
#include <cuda_fp16.h>
#include <cstdint>
#include <cstddef>

#define N_NODES 8192
#define N_EDGES 65536
#define CACHE_E 16
#define MAXDEG 256

// ================= scratch (device globals) =================
// fp16 projections [P1 | P3], [Q1 | Q2]
__device__ __half g_P_h[(size_t)N_NODES * 2048];
__device__ __half g_Q_h[(size_t)N_NODES * 1200];

// CSR by dst
__device__ int g_cnt[N_NODES];
__device__ int g_off[N_NODES];
__device__ int g_fill[N_NODES];
__device__ int g_eid[N_EDGES];

// fp16 operands
__device__ __half g_nf_h[(size_t)N_NODES * 1024];
__device__ __half g_w2v_h[(size_t)N_NODES * 320];
__device__ __half g_zf_h[(size_t)N_NODES * 1024];
__device__ __half g_zfl_h[(size_t)N_NODES * 320];
__device__ __half g_WeT_h[(size_t)2048 * 1024];
__device__ __half g_WnT_h[(size_t)2048 * 1024];
__device__ __half g_WelT_h[(size_t)1280 * 320];
__device__ __half g_WnlT_h[(size_t)768 * 320];

// ================= small helpers =================
__device__ __forceinline__ uint32_t smem_u32(const void* p) {
    uint32_t a;
    asm("{ .reg .u64 t; cvta.to.shared.u64 t, %1; cvt.u32.u64 %0, t; }" : "=r"(a) : "l"(p));
    return a;
}
__device__ __forceinline__ void cp16(uint32_t dst, const void* src) {
    asm volatile("cp.async.cg.shared.global [%0], [%1], 16;" :: "r"(dst), "l"(src) : "memory");
}
__device__ __forceinline__ void cp_commit() {
    asm volatile("cp.async.commit_group;" ::: "memory");
}
__device__ __forceinline__ void ldmx4(uint32_t* r, uint32_t addr) {
    asm volatile("ldmatrix.sync.aligned.m8n8.x4.shared.b16 {%0,%1,%2,%3}, [%4];"
                 : "=r"(r[0]), "=r"(r[1]), "=r"(r[2]), "=r"(r[3]) : "r"(addr));
}
__device__ __forceinline__ void mma_f16(float* c, const uint32_t* a, const uint32_t* b) {
    asm volatile(
        "mma.sync.aligned.m16n8k16.row.col.f32.f16.f16.f32 "
        "{%0,%1,%2,%3}, {%4,%5,%6,%7}, {%8,%9}, {%0,%1,%2,%3};"
        : "+f"(c[0]), "+f"(c[1]), "+f"(c[2]), "+f"(c[3])
        : "r"(a[0]), "r"(a[1]), "r"(a[2]), "r"(a[3]), "r"(b[0]), "r"(b[1]));
}
__device__ __forceinline__ float4 h4_to_f4(uint2 pk) {
    __half2 h0 = *(__half2*)&pk.x;
    __half2 h1 = *(__half2*)&pk.y;
    float2 f0 = __half22float2(h0);
    float2 f1 = __half22float2(h1);
    return make_float4(f0.x, f0.y, f1.x, f1.y);
}

// ================= plain fp16 HMMA GEMM =================
// C (fp32) or Ch (fp16) = A1@B1^T + A2@B2^T (+bias, relu)
#define KC 64
#define TILE_B 16384
#define STAGE_B (2 * TILE_B)
#define GEMM_SMEM (2 * STAGE_B)

__device__ __forceinline__ void issue_chunk(
    uint32_t sb_stage,
    const __half* A, const __half* B,
    int ldA, int ldB, int rowBase, int colBase, int k0, int tid)
{
#pragma unroll
    for (int t = 0; t < 2; ++t) {
        const __half* src = (t == 0) ? A : B;
        const int row0 = (t == 0) ? rowBase : colBase;
        const int ld = (t == 0) ? ldA : ldB;
        const uint32_t tb = sb_stage + t * TILE_B;
#pragma unroll
        for (int i = 0; i < 4; ++i) {
            int idx = i * 256 + tid;
            int r = idx >> 3;
            int cch = idx & 7;
            uint32_t dst = tb + r * 128 + (((cch ^ (r & 7))) << 4);
            cp16(dst, src + (size_t)(row0 + r) * ld + k0 + cch * 8);
        }
    }
}

__global__ __launch_bounds__(256, 2) void mma_gemm(
    float* __restrict__ C, __half* __restrict__ Ch, int ldc, int Nvalid,
    const __half* __restrict__ A1, const __half* __restrict__ B1, int K1,
    const __half* __restrict__ A2, const __half* __restrict__ B2, int K2,
    const float* __restrict__ bias, int do_relu)
{
    extern __shared__ char smem[];
    const uint32_t sb = smem_u32(smem);
    const int tid = threadIdx.x;
    const int wid = tid >> 5;
    const int lane = tid & 31;
    const int warp_m = wid & 3;
    const int warp_n = wid >> 2;
    const int rowBase = blockIdx.y * 128;
    const int colBase = blockIdx.x * 128;

    float c[2][8][4];
#pragma unroll
    for (int i = 0; i < 2; ++i)
#pragma unroll
        for (int j = 0; j < 8; ++j)
#pragma unroll
            for (int k = 0; k < 4; ++k) c[i][j][k] = 0.f;

    const int NC1 = K1 / KC;
    const int NC2 = K2 / KC;
    const int NC = NC1 + NC2;

    issue_chunk(sb, A1, B1, K1, K1, rowBase, colBase, 0, tid);
    cp_commit();

#pragma unroll 1
    for (int ch = 0; ch < NC; ++ch) {
        const uint32_t cur = sb + (uint32_t)(ch & 1) * STAGE_B;
        if (ch + 1 < NC) {
            int nc = ch + 1;
            if (nc < NC1)
                issue_chunk(sb + (uint32_t)(nc & 1) * STAGE_B, A1, B1,
                            K1, K1, rowBase, colBase, nc * KC, tid);
            else
                issue_chunk(sb + (uint32_t)(nc & 1) * STAGE_B, A2, B2,
                            K2, K2, rowBase, colBase, (nc - NC1) * KC, tid);
            cp_commit();
            asm volatile("cp.async.wait_group 1;" ::: "memory");
        } else {
            asm volatile("cp.async.wait_group 0;" ::: "memory");
        }
        __syncthreads();

#pragma unroll
        for (int ks = 0; ks < 4; ++ks) {
            uint32_t ah[2][4], bh[4][4];
#pragma unroll
            for (int mf = 0; mf < 2; ++mf) {
                int row = warp_m * 32 + mf * 16 + ((lane >> 3) & 1) * 8 + (lane & 7);
                int chunk = ks * 2 + (lane >> 4);
                uint32_t ad = cur + row * 128 + ((chunk ^ (row & 7)) << 4);
                ldmx4(ah[mf], ad);
            }
#pragma unroll
            for (int nf2 = 0; nf2 < 4; ++nf2) {
                int row = warp_n * 64 + nf2 * 16 + (lane >> 4) * 8 + (lane & 7);
                int chunk = ks * 2 + ((lane >> 3) & 1);
                uint32_t bd = cur + TILE_B + row * 128 + ((chunk ^ (row & 7)) << 4);
                ldmx4(bh[nf2], bd);
            }
#pragma unroll
            for (int mf = 0; mf < 2; ++mf)
#pragma unroll
                for (int nf = 0; nf < 8; ++nf)
                    mma_f16(c[mf][nf], ah[mf], &bh[nf >> 1][(nf & 1) * 2]);
        }
        __syncthreads();
    }

    const int r0 = rowBase + warp_m * 32 + (lane >> 2);
    const int colb = colBase + warp_n * 64 + (lane & 3) * 2;
#pragma unroll
    for (int mf = 0; mf < 2; ++mf) {
        int row = r0 + mf * 16;
#pragma unroll
        for (int nf = 0; nf < 8; ++nf) {
            int col = colb + nf * 8;
            if (col < Nvalid) {
                float b0 = 0.f, b1 = 0.f;
                if (bias) { b0 = bias[col]; b1 = bias[col + 1]; }
                float2 v0, v1;
                v0.x = c[mf][nf][0] + b0; v0.y = c[mf][nf][1] + b1;
                v1.x = c[mf][nf][2] + b0; v1.y = c[mf][nf][3] + b1;
                if (do_relu) {
                    v0.x = fmaxf(v0.x, 0.f); v0.y = fmaxf(v0.y, 0.f);
                    v1.x = fmaxf(v1.x, 0.f); v1.y = fmaxf(v1.y, 0.f);
                }
                if (Ch) {
                    __half2 h0 = __floats2half2_rn(v0.x, v0.y);
                    __half2 h1 = __floats2half2_rn(v1.x, v1.y);
                    *(__half2*)(Ch + (size_t)row * ldc + col) = h0;
                    *(__half2*)(Ch + (size_t)(row + 8) * ldc + col) = h1;
                } else {
                    *(float2*)(C + (size_t)row * ldc + col) = v0;
                    *(float2*)(C + (size_t)(row + 8) * ldc + col) = v1;
                }
            }
        }
    }
}

// ================= conversion kernels =================
__global__ void round_rows(const float* __restrict__ src, int M, int Ks, int Kd,
                           __half* __restrict__ hi) {
    size_t total = (size_t)M * Kd;
    size_t stride = (size_t)gridDim.x * blockDim.x;
    for (size_t i = (size_t)blockIdx.x * blockDim.x + threadIdx.x; i < total; i += stride) {
        int row = (int)(i / Kd);
        int col = (int)(i % Kd);
        float v = (col < Ks) ? src[(size_t)row * Ks + col] : 0.f;
        hi[i] = __float2half_rn(v);
    }
}

__global__ void transpose_round(const float* __restrict__ W, int ldw, int K, int N,
                                __half* __restrict__ hi, int Kd, int n0) {
    __shared__ float tile[32][33];
    int kb = blockIdx.y * 32, nb = blockIdx.x * 32;
#pragma unroll
    for (int i = 0; i < 4; ++i) {
        int k = kb + threadIdx.y + i * 8;
        int n = nb + threadIdx.x;
        tile[threadIdx.y + i * 8][threadIdx.x] = (k < K && n < N) ? W[(size_t)k * ldw + n] : 0.f;
    }
    __syncthreads();
#pragma unroll
    for (int i = 0; i < 4; ++i) {
        int n = nb + threadIdx.y + i * 8;
        int k = kb + threadIdx.x;
        if (n < N && k < Kd)
            hi[(size_t)(n0 + n) * Kd + k] = __float2half_rn(tile[threadIdx.x][threadIdx.y + i * 8]);
    }
}

// ================= CSR construction =================
__global__ void zero_cnt_kernel() {
    int i = blockIdx.x * blockDim.x + threadIdx.x;
    if (i < N_NODES) g_cnt[i] = 0;
}
__global__ void hist_kernel(const int* __restrict__ dst) {
    int e = blockIdx.x * blockDim.x + threadIdx.x;
    if (e < N_EDGES) atomicAdd(&g_cnt[dst[e]], 1);
}
__global__ __launch_bounds__(1024) void scan_kernel() {
    __shared__ int sm[1024];
    int t = threadIdx.x;
    int loc[8];
    int s = 0;
#pragma unroll
    for (int i = 0; i < 8; ++i) { loc[i] = g_cnt[t * 8 + i]; s += loc[i]; }
    sm[t] = s;
    __syncthreads();
    for (int off = 1; off < 1024; off <<= 1) {
        int v = sm[t];
        if (t >= off) v += sm[t - off];
        __syncthreads();
        sm[t] = v;
        __syncthreads();
    }
    int run = (t == 0) ? 0 : sm[t - 1];
#pragma unroll
    for (int i = 0; i < 8; ++i) {
        g_off[t * 8 + i] = run;
        g_fill[t * 8 + i] = run;
        run += loc[i];
    }
}
__global__ void fill_kernel(const int* __restrict__ dst) {
    int e = blockIdx.x * blockDim.x + threadIdx.x;
    if (e < N_EDGES) {
        int pos = atomicAdd(&g_fill[dst[e]], 1);
        g_eid[pos] = e;
    }
}

// ================= merged score+softmax+combine kernel (block per dst node) =================
__global__ __launch_bounds__(256) void combine_all(
    const float* __restrict__ n_f, const float* __restrict__ w2v,
    const float* __restrict__ s_f, const int* __restrict__ src,
    const float* __restrict__ We, const float* __restrict__ be,
    const float* __restrict__ Wa,
    const float* __restrict__ bel, const float* __restrict__ Wal)
{
    extern __shared__ __half efc[];   // CACHE_E * 1024 halves (32 KB)
    const int d = blockIdx.x;
    const int t = threadIdx.x;
    const int lane = t & 31;
    const int deg = g_cnt[d];
    const int start = g_off[d];

    __shared__ int sm_eid[MAXDEG], sm_src[MAXDEG];
    __shared__ float sm_af[MAXDEG], sm_afl[MAXDEG];
    __shared__ float sm_scal[4];

    for (int i = t; i < deg; i += 256) {
        int e = g_eid[start + i];
        sm_eid[i] = e;
        sm_src[i] = src[e];
    }
    for (int i = t; i < MAXDEG; i += 256) { sm_af[i] = 0.f; sm_afl[i] = 0.f; }
    __syncthreads();

    const float4* Ws4 = (const float4*)(We + (size_t)1024 * 1024);

    float4 wsr[16];
#pragma unroll
    for (int k = 0; k < 16; ++k) wsr[k] = Ws4[k * 256 + t];

    // p3r = P3[d] + be (fp16 P)
    float4 p3r;
    {
        uint2 pr = *(const uint2*)(g_P_h + (size_t)d * 2048 + 1024 + 4 * t);
        p3r = h4_to_f4(pr);
        float4 ber = ((const float4*)be)[t];
        p3r.x += ber.x; p3r.y += ber.y; p3r.z += ber.z; p3r.w += ber.w;
    }
    float4 war = ((const float4*)Wa)[t];
    float4 q2r = make_float4(0.f, 0.f, 0.f, 0.f);
    float4 walr = make_float4(0.f, 0.f, 0.f, 0.f);
    if (t < 150) {
        uint2 qr = *(const uint2*)(g_Q_h + (size_t)d * 1200 + 600 + 4 * t);
        q2r = h4_to_f4(qr);
        float4 belr = ((const float4*)bel)[t];
        q2r.x += belr.x; q2r.y += belr.y; q2r.z += belr.z; q2r.w += belr.w;
        walr = ((const float4*)Wal)[t];
    }

    // ---------- Phase A: e_f + scores ----------
#pragma unroll 1
    for (int i = 0; i < deg; ++i) {
        const int eid = sm_eid[i];
        const int s = sm_src[i];

        uint2 pr = *(const uint2*)(g_P_h + (size_t)s * 2048 + 4 * t);
        float4 v = h4_to_f4(pr);
        v.x += p3r.x; v.y += p3r.y; v.z += p3r.z; v.w += p3r.w;
#pragma unroll
        for (int k = 0; k < 16; ++k) {
            float sv = __ldg(&s_f[(size_t)eid * 16 + k]);
            v.x = fmaf(sv, wsr[k].x, v.x); v.y = fmaf(sv, wsr[k].y, v.y);
            v.z = fmaf(sv, wsr[k].z, v.z); v.w = fmaf(sv, wsr[k].w, v.w);
        }
        v.x = fmaxf(v.x, 0.f); v.y = fmaxf(v.y, 0.f);
        v.z = fmaxf(v.z, 0.f); v.w = fmaxf(v.w, 0.f);
        if (i < CACHE_E) {
            __half2 h0 = __floats2half2_rn(v.x, v.y);
            __half2 h1 = __floats2half2_rn(v.z, v.w);
            uint2 pk;
            pk.x = *(uint32_t*)&h0;
            pk.y = *(uint32_t*)&h1;
            *(uint2*)(efc + i * 1024 + 4 * t) = pk;
        }

        float acc = v.x * war.x + v.y * war.y + v.z * war.z + v.w * war.w;

        float accl = 0.f;
        if (t < 150) {
            uint2 qr = *(const uint2*)(g_Q_h + (size_t)s * 1200 + 4 * t);
            float4 u = h4_to_f4(qr);
            u.x += q2r.x; u.y += q2r.y; u.z += q2r.z; u.w += q2r.w;
            u.x = fmaxf(u.x, 0.f); u.y = fmaxf(u.y, 0.f);
            u.z = fmaxf(u.z, 0.f); u.w = fmaxf(u.w, 0.f);
            accl = u.x * walr.x + u.y * walr.y + u.z * walr.z + u.w * walr.w;
        }

#pragma unroll
        for (int off = 16; off > 0; off >>= 1) {
            acc += __shfl_down_sync(0xffffffffu, acc, off);
            accl += __shfl_down_sync(0xffffffffu, accl, off);
        }
        if (lane == 0) {
            atomicAdd(&sm_af[i], acc);
            if (accl != 0.f) atomicAdd(&sm_afl[i], accl);
        }
    }
    __syncthreads();

    // ---------- softmax scalars (warp 0) ----------
    if (t < 32) {
        float m = -1e30f, ml = -1e30f;
        for (int i = t; i < deg; i += 32) {
            m = fmaxf(m, sm_af[i]);
            ml = fmaxf(ml, sm_afl[i]);
        }
#pragma unroll
        for (int off = 16; off > 0; off >>= 1) {
            m = fmaxf(m, __shfl_xor_sync(0xffffffffu, m, off));
            ml = fmaxf(ml, __shfl_xor_sync(0xffffffffu, ml, off));
        }
        float den = 0.f, denl = 0.f;
        for (int i = t; i < deg; i += 32) {
            den += expf(sm_af[i] - m);
            denl += expf(sm_afl[i] - ml);
        }
#pragma unroll
        for (int off = 16; off > 0; off >>= 1) {
            den += __shfl_xor_sync(0xffffffffu, den, off);
            denl += __shfl_xor_sync(0xffffffffu, denl, off);
        }
        if (t == 0) {
            sm_scal[0] = m;
            sm_scal[1] = (deg > 0) ? 1.f / den : 0.f;
            sm_scal[2] = ml;
            sm_scal[3] = (deg > 0) ? 1.f / denl : 0.f;
        }
    }
    __syncthreads();

    {
        const float m = sm_scal[0], rden = sm_scal[1];
        const float ml = sm_scal[2], rdenl = sm_scal[3];
        for (int i = t; i < deg; i += 256) {
            sm_af[i] = expf(sm_af[i] - m) * rden;
            sm_afl[i] = expf(sm_afl[i] - ml) * rdenl;
        }
    }
    __syncthreads();

    // ---------- Phase B: weighted accumulate (fp16 gathers) ----------
    float4 acc = make_float4(0.f, 0.f, 0.f, 0.f);
    float4 accl = make_float4(0.f, 0.f, 0.f, 0.f);

#pragma unroll 1
    for (int i = 0; i < deg; ++i) {
        const int s = sm_src[i];
        const float alpha = sm_af[i];
        const float alphal = sm_afl[i];

        float4 v;
        if (i < CACHE_E) {
            uint2 pk = *(const uint2*)(efc + i * 1024 + 4 * t);
            v = h4_to_f4(pk);
        } else {
            const int eid = sm_eid[i];
            uint2 pr = *(const uint2*)(g_P_h + (size_t)s * 2048 + 4 * t);
            v = h4_to_f4(pr);
            v.x += p3r.x; v.y += p3r.y; v.z += p3r.z; v.w += p3r.w;
#pragma unroll
            for (int k = 0; k < 16; ++k) {
                float sv = __ldg(&s_f[(size_t)eid * 16 + k]);
                v.x = fmaf(sv, wsr[k].x, v.x); v.y = fmaf(sv, wsr[k].y, v.y);
                v.z = fmaf(sv, wsr[k].z, v.z); v.w = fmaf(sv, wsr[k].w, v.w);
            }
            v.x = fmaxf(v.x, 0.f); v.y = fmaxf(v.y, 0.f);
            v.z = fmaxf(v.z, 0.f); v.w = fmaxf(v.w, 0.f);
        }

        uint2 nraw = *(const uint2*)(g_nf_h + (size_t)s * 1024 + 4 * t);
        float4 n = h4_to_f4(nraw);
        acc.x = fmaf(alpha, n.x + v.x, acc.x);
        acc.y = fmaf(alpha, n.y + v.y, acc.y);
        acc.z = fmaf(alpha, n.z + v.z, acc.z);
        acc.w = fmaf(alpha, n.w + v.w, acc.w);

        if (t < 75) {
            uint2 wraw = *(const uint2*)(g_w2v_h + (size_t)s * 320 + 4 * t);
            float4 w = h4_to_f4(wraw);
            accl.x = fmaf(alphal, w.x, accl.x);
            accl.y = fmaf(alphal, w.y, accl.y);
            accl.z = fmaf(alphal, w.z, accl.z);
            accl.w = fmaf(alphal, w.w, accl.w);
        }
    }

    // ---------- write fp16 ----------
    {
        size_t o = (size_t)d * 1024 + 4 * t;
        g_zf_h[o + 0] = __float2half_rn(acc.x);
        g_zf_h[o + 1] = __float2half_rn(acc.y);
        g_zf_h[o + 2] = __float2half_rn(acc.z);
        g_zf_h[o + 3] = __float2half_rn(acc.w);
    }
    if (t < 75) {
        size_t o = (size_t)d * 320 + 4 * t;
        g_zfl_h[o + 0] = __float2half_rn(accl.x);
        g_zfl_h[o + 1] = __float2half_rn(accl.y);
        g_zfl_h[o + 2] = __float2half_rn(accl.z);
        g_zfl_h[o + 3] = __float2half_rn(accl.w);
    }
}

// ================= launch =================
extern "C" void kernel_launch(void* const* d_in, const int* in_sizes, int n_in,
                              void* d_out, int out_size) {
    const float* n_f  = (const float*)d_in[0];
    const float* w2v  = (const float*)d_in[1];
    const float* s_f  = (const float*)d_in[2];
    const int*   src  = (const int*)d_in[3];
    const int*   dst  = (const int*)d_in[4];
    const float* We   = (const float*)d_in[5];
    const float* be   = (const float*)d_in[6];
    const float* Wel  = (const float*)d_in[7];
    const float* bel  = (const float*)d_in[8];
    const float* Wa   = (const float*)d_in[9];
    const float* Wal  = (const float*)d_in[11];
    const float* Wn   = (const float*)d_in[13];
    const float* bn   = (const float*)d_in[14];
    const float* Wnl  = (const float*)d_in[15];
    const float* bnl  = (const float*)d_in[16];

    float* out      = (float*)d_out;
    float* out_lang = out + (size_t)N_NODES * 1024;

    __half *P_h, *Q_h;
    __half *nf_h, *w2v_h, *zf_h, *zfl_h;
    __half *WeT_h, *WnT_h, *WelT_h, *WnlT_h;
    cudaGetSymbolAddress((void**)&P_h, g_P_h);
    cudaGetSymbolAddress((void**)&Q_h, g_Q_h);
    cudaGetSymbolAddress((void**)&nf_h, g_nf_h);
    cudaGetSymbolAddress((void**)&w2v_h, g_w2v_h);
    cudaGetSymbolAddress((void**)&zf_h, g_zf_h);
    cudaGetSymbolAddress((void**)&zfl_h, g_zfl_h);
    cudaGetSymbolAddress((void**)&WeT_h, g_WeT_h);
    cudaGetSymbolAddress((void**)&WnT_h, g_WnT_h);
    cudaGetSymbolAddress((void**)&WelT_h, g_WelT_h);
    cudaGetSymbolAddress((void**)&WnlT_h, g_WnlT_h);

    cudaFuncSetAttribute(mma_gemm, cudaFuncAttributeMaxDynamicSharedMemorySize, GEMM_SMEM);
    cudaFuncSetAttribute(combine_all, cudaFuncAttributeMaxDynamicSharedMemorySize,
                         CACHE_E * 1024 * sizeof(__half));

    dim3 tblk(32, 8);

    // conversions
    round_rows<<<2048, 256>>>(n_f, N_NODES, 1024, 1024, nf_h);
    round_rows<<<1024, 256>>>(w2v, N_NODES, 300, 320, w2v_h);
    transpose_round<<<dim3(32, 32), tblk>>>(We, 1024, 1024, 1024, WeT_h, 1024, 0);
    transpose_round<<<dim3(32, 32), tblk>>>(We + (size_t)1040 * 1024, 1024, 1024, 1024,
                                            WeT_h, 1024, 1024);
    transpose_round<<<dim3(19, 10), tblk>>>(Wel, 600, 300, 600, WelT_h, 320, 0);
    transpose_round<<<dim3(19, 10), tblk>>>(Wel + (size_t)300 * 600, 600, 300, 600,
                                            WelT_h, 320, 600);
    transpose_round<<<dim3(32, 32), tblk>>>(Wn, 1024, 1024, 1024, WnT_h, 1024, 0);
    transpose_round<<<dim3(32, 32), tblk>>>(Wn + (size_t)1024 * 1024, 1024, 1024, 1024,
                                            WnT_h, 1024, 1024);
    transpose_round<<<dim3(10, 10), tblk>>>(Wnl, 300, 300, 300, WnlT_h, 320, 0);
    transpose_round<<<dim3(10, 10), tblk>>>(Wnl + (size_t)300 * 300, 300, 300, 300,
                                            WnlT_h, 320, 300);

    // CSR
    zero_cnt_kernel<<<8, 1024>>>();
    hist_kernel<<<64, 1024>>>(dst);
    scan_kernel<<<1, 1024>>>();
    fill_kernel<<<64, 1024>>>(dst);

    // node projections (fp16 output)
    mma_gemm<<<dim3(16, 64), 256, GEMM_SMEM>>>(nullptr, P_h, 2048, 2048,
        nf_h, WeT_h, 1024, nullptr, nullptr, 0, nullptr, 0);
    mma_gemm<<<dim3(10, 64), 256, GEMM_SMEM>>>(nullptr, Q_h, 1200, 1200,
        w2v_h, WelT_h, 320, nullptr, nullptr, 0, nullptr, 0);

    // merged edge scores + softmax + aggregate
    combine_all<<<N_NODES, 256, CACHE_E * 1024 * sizeof(__half)>>>(
        n_f, w2v, s_f, src, We, be, Wa, bel, Wal);

    // node apply (fp32 output to d_out)
    mma_gemm<<<dim3(8, 64), 256, GEMM_SMEM>>>(out, nullptr, 1024, 1024,
        nf_h, WnT_h, 1024,
        zf_h, WnT_h + (size_t)1024 * 1024, 1024,
        bn, 1);
    mma_gemm<<<dim3(3, 64), 256, GEMM_SMEM>>>(out_lang, nullptr, 300, 300,
        w2v_h, WnlT_h, 320,
        zfl_h, WnlT_h + (size_t)300 * 320, 320,
        bnl, 1);
}

// round 12
// speedup vs baseline: 1.1868x; 1.0506x over previous
#include <cuda_runtime.h>
#include <cuda_fp16.h>
#include <cstdint>
#include <cstddef>

#define N_NODES 8192
#define N_EDGES 65536
#define CACHE_E 16
#define MAXDEG 256

// ================= scratch (device globals) =================
__device__ __half g_P_h[(size_t)N_NODES * 2048];   // [P1 | P3]
__device__ __half g_Q_h[(size_t)N_NODES * 1200];   // [Q1 | Q2]

// CSR by dst
__device__ int g_cnt[N_NODES];
__device__ int g_off[N_NODES];
__device__ int g_fill[N_NODES];
__device__ int g_eid[N_EDGES];

// fp16 operands
__device__ __half g_nf_h[(size_t)N_NODES * 1024];
__device__ __half g_w2v_h[(size_t)N_NODES * 320];
__device__ __half g_zf_h[(size_t)N_NODES * 1024];
__device__ __half g_zfl_h[(size_t)N_NODES * 320];
__device__ __half g_WeT_h[(size_t)2048 * 1024];
__device__ __half g_WnT_h[(size_t)2048 * 1024];
__device__ __half g_WelT_h[(size_t)1280 * 320];
__device__ __half g_WnlT_h[(size_t)768 * 320];

// ================= small helpers =================
__device__ __forceinline__ uint32_t smem_u32(const void* p) {
    uint32_t a;
    asm("{ .reg .u64 t; cvta.to.shared.u64 t, %1; cvt.u32.u64 %0, t; }" : "=r"(a) : "l"(p));
    return a;
}
__device__ __forceinline__ void cp16(uint32_t dst, const void* src) {
    asm volatile("cp.async.cg.shared.global [%0], [%1], 16;" :: "r"(dst), "l"(src) : "memory");
}
__device__ __forceinline__ void cp_commit() {
    asm volatile("cp.async.commit_group;" ::: "memory");
}
__device__ __forceinline__ void ldmx4(uint32_t* r, uint32_t addr) {
    asm volatile("ldmatrix.sync.aligned.m8n8.x4.shared.b16 {%0,%1,%2,%3}, [%4];"
                 : "=r"(r[0]), "=r"(r[1]), "=r"(r[2]), "=r"(r[3]) : "r"(addr));
}
__device__ __forceinline__ void mma_f16(float* c, const uint32_t* a, const uint32_t* b) {
    asm volatile(
        "mma.sync.aligned.m16n8k16.row.col.f32.f16.f16.f32 "
        "{%0,%1,%2,%3}, {%4,%5,%6,%7}, {%8,%9}, {%0,%1,%2,%3};"
        : "+f"(c[0]), "+f"(c[1]), "+f"(c[2]), "+f"(c[3])
        : "r"(a[0]), "r"(a[1]), "r"(a[2]), "r"(a[3]), "r"(b[0]), "r"(b[1]));
}
__device__ __forceinline__ float4 h4_to_f4(uint2 pk) {
    __half2 h0 = *(__half2*)&pk.x;
    __half2 h1 = *(__half2*)&pk.y;
    float2 f0 = __half22float2(h0);
    float2 f1 = __half22float2(h1);
    return make_float4(f0.x, f0.y, f1.x, f1.y);
}

// ================= plain fp16 HMMA GEMM =================
#define KC 64
#define TILE_B 16384
#define STAGE_B (2 * TILE_B)
#define GEMM_SMEM (2 * STAGE_B)

__device__ __forceinline__ void issue_chunk(
    uint32_t sb_stage,
    const __half* A, const __half* B,
    int ldA, int ldB, int rowBase, int colBase, int k0, int tid)
{
#pragma unroll
    for (int t = 0; t < 2; ++t) {
        const __half* src = (t == 0) ? A : B;
        const int row0 = (t == 0) ? rowBase : colBase;
        const int ld = (t == 0) ? ldA : ldB;
        const uint32_t tb = sb_stage + t * TILE_B;
#pragma unroll
        for (int i = 0; i < 4; ++i) {
            int idx = i * 256 + tid;
            int r = idx >> 3;
            int cch = idx & 7;
            uint32_t dst = tb + r * 128 + (((cch ^ (r & 7))) << 4);
            cp16(dst, src + (size_t)(row0 + r) * ld + k0 + cch * 8);
        }
    }
}

__global__ __launch_bounds__(256, 2) void mma_gemm(
    float* __restrict__ C, __half* __restrict__ Ch, int ldc, int Nvalid,
    const __half* __restrict__ A1, const __half* __restrict__ B1, int K1,
    const __half* __restrict__ A2, const __half* __restrict__ B2, int K2,
    const float* __restrict__ bias, int do_relu)
{
    extern __shared__ char smem[];
    const uint32_t sb = smem_u32(smem);
    const int tid = threadIdx.x;
    const int wid = tid >> 5;
    const int lane = tid & 31;
    const int warp_m = wid & 3;
    const int warp_n = wid >> 2;
    const int rowBase = blockIdx.y * 128;
    const int colBase = blockIdx.x * 128;

    float c[2][8][4];
#pragma unroll
    for (int i = 0; i < 2; ++i)
#pragma unroll
        for (int j = 0; j < 8; ++j)
#pragma unroll
            for (int k = 0; k < 4; ++k) c[i][j][k] = 0.f;

    const int NC1 = K1 / KC;
    const int NC2 = K2 / KC;
    const int NC = NC1 + NC2;

    issue_chunk(sb, A1, B1, K1, K1, rowBase, colBase, 0, tid);
    cp_commit();

#pragma unroll 1
    for (int ch = 0; ch < NC; ++ch) {
        const uint32_t cur = sb + (uint32_t)(ch & 1) * STAGE_B;
        if (ch + 1 < NC) {
            int nc = ch + 1;
            if (nc < NC1)
                issue_chunk(sb + (uint32_t)(nc & 1) * STAGE_B, A1, B1,
                            K1, K1, rowBase, colBase, nc * KC, tid);
            else
                issue_chunk(sb + (uint32_t)(nc & 1) * STAGE_B, A2, B2,
                            K2, K2, rowBase, colBase, (nc - NC1) * KC, tid);
            cp_commit();
            asm volatile("cp.async.wait_group 1;" ::: "memory");
        } else {
            asm volatile("cp.async.wait_group 0;" ::: "memory");
        }
        __syncthreads();

#pragma unroll
        for (int ks = 0; ks < 4; ++ks) {
            uint32_t ah[2][4], bh[4][4];
#pragma unroll
            for (int mf = 0; mf < 2; ++mf) {
                int row = warp_m * 32 + mf * 16 + ((lane >> 3) & 1) * 8 + (lane & 7);
                int chunk = ks * 2 + (lane >> 4);
                uint32_t ad = cur + row * 128 + ((chunk ^ (row & 7)) << 4);
                ldmx4(ah[mf], ad);
            }
#pragma unroll
            for (int nf2 = 0; nf2 < 4; ++nf2) {
                int row = warp_n * 64 + nf2 * 16 + (lane >> 4) * 8 + (lane & 7);
                int chunk = ks * 2 + ((lane >> 3) & 1);
                uint32_t bd = cur + TILE_B + row * 128 + ((chunk ^ (row & 7)) << 4);
                ldmx4(bh[nf2], bd);
            }
#pragma unroll
            for (int mf = 0; mf < 2; ++mf)
#pragma unroll
                for (int nf = 0; nf < 8; ++nf)
                    mma_f16(c[mf][nf], ah[mf], &bh[nf >> 1][(nf & 1) * 2]);
        }
        __syncthreads();
    }

    const int r0 = rowBase + warp_m * 32 + (lane >> 2);
    const int colb = colBase + warp_n * 64 + (lane & 3) * 2;
#pragma unroll
    for (int mf = 0; mf < 2; ++mf) {
        int row = r0 + mf * 16;
#pragma unroll
        for (int nf = 0; nf < 8; ++nf) {
            int col = colb + nf * 8;
            if (col < Nvalid) {
                float b0 = 0.f, b1 = 0.f;
                if (bias) { b0 = bias[col]; b1 = bias[col + 1]; }
                float2 v0, v1;
                v0.x = c[mf][nf][0] + b0; v0.y = c[mf][nf][1] + b1;
                v1.x = c[mf][nf][2] + b0; v1.y = c[mf][nf][3] + b1;
                if (do_relu) {
                    v0.x = fmaxf(v0.x, 0.f); v0.y = fmaxf(v0.y, 0.f);
                    v1.x = fmaxf(v1.x, 0.f); v1.y = fmaxf(v1.y, 0.f);
                }
                if (Ch) {
                    __half2 h0 = __floats2half2_rn(v0.x, v0.y);
                    __half2 h1 = __floats2half2_rn(v1.x, v1.y);
                    *(__half2*)(Ch + (size_t)row * ldc + col) = h0;
                    *(__half2*)(Ch + (size_t)(row + 8) * ldc + col) = h1;
                } else {
                    *(float2*)(C + (size_t)row * ldc + col) = v0;
                    *(float2*)(C + (size_t)(row + 8) * ldc + col) = v1;
                }
            }
        }
    }
}

// ================= conversion kernels (merged) =================
// nf (8192x1024, no pad) + w2v (8192x300 -> 320 pad) in one launch
__global__ void round_rows2(const float* __restrict__ a, __half* __restrict__ ah,
                            const float* __restrict__ b, __half* __restrict__ bh) {
    const size_t T1 = (size_t)N_NODES * 1024;
    const size_t T2 = (size_t)N_NODES * 320;
    size_t stride = (size_t)gridDim.x * blockDim.x;
    for (size_t i = (size_t)blockIdx.x * blockDim.x + threadIdx.x; i < T1 + T2; i += stride) {
        if (i < T1) {
            ah[i] = __float2half_rn(a[i]);
        } else {
            size_t j = i - T1;
            int row = (int)(j / 320);
            int col = (int)(j % 320);
            float v = (col < 300) ? b[(size_t)row * 300 + col] : 0.f;
            bh[j] = __float2half_rn(v);
        }
    }
}

// paired transpose: z=0 -> (W0, n0_0), z=1 -> (W1, n0_1)
__global__ void transpose_round2(const float* __restrict__ W0, const float* __restrict__ W1,
                                 int ldw, int K, int N,
                                 __half* __restrict__ hi, int Kd, int n0_0, int n0_1) {
    const float* W = blockIdx.z ? W1 : W0;
    const int n0 = blockIdx.z ? n0_1 : n0_0;
    __shared__ float tile[32][33];
    int kb = blockIdx.y * 32, nb = blockIdx.x * 32;
#pragma unroll
    for (int i = 0; i < 4; ++i) {
        int k = kb + threadIdx.y + i * 8;
        int n = nb + threadIdx.x;
        tile[threadIdx.y + i * 8][threadIdx.x] = (k < K && n < N) ? W[(size_t)k * ldw + n] : 0.f;
    }
    __syncthreads();
#pragma unroll
    for (int i = 0; i < 4; ++i) {
        int n = nb + threadIdx.y + i * 8;
        int k = kb + threadIdx.x;
        if (n < N && k < Kd)
            hi[(size_t)(n0 + n) * Kd + k] = __float2half_rn(tile[threadIdx.x][threadIdx.y + i * 8]);
    }
}

// ================= CSR construction =================
__global__ void zero_cnt_kernel() {
    int i = blockIdx.x * blockDim.x + threadIdx.x;
    if (i < N_NODES) g_cnt[i] = 0;
}
__global__ void hist_kernel(const int* __restrict__ dst) {
    int e = blockIdx.x * blockDim.x + threadIdx.x;
    if (e < N_EDGES) atomicAdd(&g_cnt[dst[e]], 1);
}
__global__ __launch_bounds__(1024) void scan_kernel() {
    __shared__ int sm[1024];
    int t = threadIdx.x;
    int loc[8];
    int s = 0;
#pragma unroll
    for (int i = 0; i < 8; ++i) { loc[i] = g_cnt[t * 8 + i]; s += loc[i]; }
    sm[t] = s;
    __syncthreads();
    for (int off = 1; off < 1024; off <<= 1) {
        int v = sm[t];
        if (t >= off) v += sm[t - off];
        __syncthreads();
        sm[t] = v;
        __syncthreads();
    }
    int run = (t == 0) ? 0 : sm[t - 1];
#pragma unroll
    for (int i = 0; i < 8; ++i) {
        g_off[t * 8 + i] = run;
        g_fill[t * 8 + i] = run;
        run += loc[i];
    }
}
__global__ void fill_kernel(const int* __restrict__ dst) {
    int e = blockIdx.x * blockDim.x + threadIdx.x;
    if (e < N_EDGES) {
        int pos = atomicAdd(&g_fill[dst[e]], 1);
        g_eid[pos] = e;
    }
}

// ================= merged score+softmax+combine kernel =================
__global__ __launch_bounds__(256) void combine_all(
    const float* __restrict__ n_f, const float* __restrict__ w2v,
    const float* __restrict__ s_f, const int* __restrict__ src,
    const float* __restrict__ We, const float* __restrict__ be,
    const float* __restrict__ Wa,
    const float* __restrict__ bel, const float* __restrict__ Wal)
{
    extern __shared__ __half efc[];   // CACHE_E * 1024 halves (32 KB)
    const int d = blockIdx.x;
    const int t = threadIdx.x;
    const int lane = t & 31;
    const int deg = g_cnt[d];
    const int start = g_off[d];

    __shared__ int sm_eid[MAXDEG], sm_src[MAXDEG];
    __shared__ float sm_af[MAXDEG], sm_afl[MAXDEG];
    __shared__ float sm_scal[4];

    for (int i = t; i < deg; i += 256) {
        int e = g_eid[start + i];
        sm_eid[i] = e;
        sm_src[i] = src[e];
    }
    for (int i = t; i < MAXDEG; i += 256) { sm_af[i] = 0.f; sm_afl[i] = 0.f; }
    __syncthreads();

    const float4* Ws4 = (const float4*)(We + (size_t)1024 * 1024);

    float4 wsr[16];
#pragma unroll
    for (int k = 0; k < 16; ++k) wsr[k] = Ws4[k * 256 + t];

    float4 p3r;
    {
        uint2 pr = *(const uint2*)(g_P_h + (size_t)d * 2048 + 1024 + 4 * t);
        p3r = h4_to_f4(pr);
        float4 ber = ((const float4*)be)[t];
        p3r.x += ber.x; p3r.y += ber.y; p3r.z += ber.z; p3r.w += ber.w;
    }
    float4 war = ((const float4*)Wa)[t];
    float4 q2r = make_float4(0.f, 0.f, 0.f, 0.f);
    float4 walr = make_float4(0.f, 0.f, 0.f, 0.f);
    if (t < 150) {
        uint2 qr = *(const uint2*)(g_Q_h + (size_t)d * 1200 + 600 + 4 * t);
        q2r = h4_to_f4(qr);
        float4 belr = ((const float4*)bel)[t];
        q2r.x += belr.x; q2r.y += belr.y; q2r.z += belr.z; q2r.w += belr.w;
        walr = ((const float4*)Wal)[t];
    }

    // ---------- Phase A: e_f + scores (software-pipelined gathers) ----------
    uint2 pr_c = make_uint2(0u, 0u), qr_c = make_uint2(0u, 0u);
    if (deg > 0) {
        int s0 = sm_src[0];
        pr_c = *(const uint2*)(g_P_h + (size_t)s0 * 2048 + 4 * t);
        if (t < 150) qr_c = *(const uint2*)(g_Q_h + (size_t)s0 * 1200 + 4 * t);
    }

#pragma unroll 1
    for (int i = 0; i < deg; ++i) {
        const int eid = sm_eid[i];

        // issue s_f loads up front (4x float4 instead of 16 scalars)
        const float4* sf4 = (const float4*)(s_f + (size_t)eid * 16);
        float4 sv0 = __ldg(sf4 + 0), sv1 = __ldg(sf4 + 1);
        float4 sv2 = __ldg(sf4 + 2), sv3 = __ldg(sf4 + 3);

        // prefetch next edge's gathers
        uint2 pr_n = make_uint2(0u, 0u), qr_n = make_uint2(0u, 0u);
        if (i + 1 < deg) {
            int sn = sm_src[i + 1];
            pr_n = *(const uint2*)(g_P_h + (size_t)sn * 2048 + 4 * t);
            if (t < 150) qr_n = *(const uint2*)(g_Q_h + (size_t)sn * 1200 + 4 * t);
        }

        float4 v = h4_to_f4(pr_c);
        v.x += p3r.x; v.y += p3r.y; v.z += p3r.z; v.w += p3r.w;
        float sfs[16] = {sv0.x, sv0.y, sv0.z, sv0.w, sv1.x, sv1.y, sv1.z, sv1.w,
                         sv2.x, sv2.y, sv2.z, sv2.w, sv3.x, sv3.y, sv3.z, sv3.w};
#pragma unroll
        for (int k = 0; k < 16; ++k) {
            v.x = fmaf(sfs[k], wsr[k].x, v.x); v.y = fmaf(sfs[k], wsr[k].y, v.y);
            v.z = fmaf(sfs[k], wsr[k].z, v.z); v.w = fmaf(sfs[k], wsr[k].w, v.w);
        }
        v.x = fmaxf(v.x, 0.f); v.y = fmaxf(v.y, 0.f);
        v.z = fmaxf(v.z, 0.f); v.w = fmaxf(v.w, 0.f);
        if (i < CACHE_E) {
            __half2 h0 = __floats2half2_rn(v.x, v.y);
            __half2 h1 = __floats2half2_rn(v.z, v.w);
            uint2 pk;
            pk.x = *(uint32_t*)&h0;
            pk.y = *(uint32_t*)&h1;
            *(uint2*)(efc + i * 1024 + 4 * t) = pk;
        }

        float acc = v.x * war.x + v.y * war.y + v.z * war.z + v.w * war.w;

        float accl = 0.f;
        if (t < 150) {
            float4 u = h4_to_f4(qr_c);
            u.x += q2r.x; u.y += q2r.y; u.z += q2r.z; u.w += q2r.w;
            u.x = fmaxf(u.x, 0.f); u.y = fmaxf(u.y, 0.f);
            u.z = fmaxf(u.z, 0.f); u.w = fmaxf(u.w, 0.f);
            accl = u.x * walr.x + u.y * walr.y + u.z * walr.z + u.w * walr.w;
        }

#pragma unroll
        for (int off = 16; off > 0; off >>= 1) {
            acc += __shfl_down_sync(0xffffffffu, acc, off);
            accl += __shfl_down_sync(0xffffffffu, accl, off);
        }
        if (lane == 0) {
            atomicAdd(&sm_af[i], acc);
            if (accl != 0.f) atomicAdd(&sm_afl[i], accl);
        }
        pr_c = pr_n;
        qr_c = qr_n;
    }
    __syncthreads();

    // ---------- softmax scalars (warp 0) ----------
    if (t < 32) {
        float m = -1e30f, ml = -1e30f;
        for (int i = t; i < deg; i += 32) {
            m = fmaxf(m, sm_af[i]);
            ml = fmaxf(ml, sm_afl[i]);
        }
#pragma unroll
        for (int off = 16; off > 0; off >>= 1) {
            m = fmaxf(m, __shfl_xor_sync(0xffffffffu, m, off));
            ml = fmaxf(ml, __shfl_xor_sync(0xffffffffu, ml, off));
        }
        float den = 0.f, denl = 0.f;
        for (int i = t; i < deg; i += 32) {
            den += expf(sm_af[i] - m);
            denl += expf(sm_afl[i] - ml);
        }
#pragma unroll
        for (int off = 16; off > 0; off >>= 1) {
            den += __shfl_xor_sync(0xffffffffu, den, off);
            denl += __shfl_xor_sync(0xffffffffu, denl, off);
        }
        if (t == 0) {
            sm_scal[0] = m;
            sm_scal[1] = (deg > 0) ? 1.f / den : 0.f;
            sm_scal[2] = ml;
            sm_scal[3] = (deg > 0) ? 1.f / denl : 0.f;
        }
    }
    __syncthreads();

    {
        const float m = sm_scal[0], rden = sm_scal[1];
        const float ml = sm_scal[2], rdenl = sm_scal[3];
        for (int i = t; i < deg; i += 256) {
            sm_af[i] = expf(sm_af[i] - m) * rden;
            sm_afl[i] = expf(sm_afl[i] - ml) * rdenl;
        }
    }
    __syncthreads();

    // ---------- Phase B: weighted accumulate (pipelined fp16 gathers) ----------
    float4 acc = make_float4(0.f, 0.f, 0.f, 0.f);
    float4 accl = make_float4(0.f, 0.f, 0.f, 0.f);

    uint2 n_c = make_uint2(0u, 0u), w_c = make_uint2(0u, 0u);
    if (deg > 0) {
        int s0 = sm_src[0];
        n_c = *(const uint2*)(g_nf_h + (size_t)s0 * 1024 + 4 * t);
        if (t < 75) w_c = *(const uint2*)(g_w2v_h + (size_t)s0 * 320 + 4 * t);
    }

#pragma unroll 1
    for (int i = 0; i < deg; ++i) {
        const int s = sm_src[i];
        const float alpha = sm_af[i];
        const float alphal = sm_afl[i];

        uint2 n_n = make_uint2(0u, 0u), w_n = make_uint2(0u, 0u);
        if (i + 1 < deg) {
            int sn = sm_src[i + 1];
            n_n = *(const uint2*)(g_nf_h + (size_t)sn * 1024 + 4 * t);
            if (t < 75) w_n = *(const uint2*)(g_w2v_h + (size_t)sn * 320 + 4 * t);
        }

        float4 v;
        if (i < CACHE_E) {
            uint2 pk = *(const uint2*)(efc + i * 1024 + 4 * t);
            v = h4_to_f4(pk);
        } else {
            const int eid = sm_eid[i];
            uint2 pr = *(const uint2*)(g_P_h + (size_t)s * 2048 + 4 * t);
            v = h4_to_f4(pr);
            v.x += p3r.x; v.y += p3r.y; v.z += p3r.z; v.w += p3r.w;
            const float4* sf4 = (const float4*)(s_f + (size_t)eid * 16);
            float4 sv0 = __ldg(sf4 + 0), sv1 = __ldg(sf4 + 1);
            float4 sv2 = __ldg(sf4 + 2), sv3 = __ldg(sf4 + 3);
            float sfs[16] = {sv0.x, sv0.y, sv0.z, sv0.w, sv1.x, sv1.y, sv1.z, sv1.w,
                             sv2.x, sv2.y, sv2.z, sv2.w, sv3.x, sv3.y, sv3.z, sv3.w};
#pragma unroll
            for (int k = 0; k < 16; ++k) {
                v.x = fmaf(sfs[k], wsr[k].x, v.x); v.y = fmaf(sfs[k], wsr[k].y, v.y);
                v.z = fmaf(sfs[k], wsr[k].z, v.z); v.w = fmaf(sfs[k], wsr[k].w, v.w);
            }
            v.x = fmaxf(v.x, 0.f); v.y = fmaxf(v.y, 0.f);
            v.z = fmaxf(v.z, 0.f); v.w = fmaxf(v.w, 0.f);
        }

        float4 n = h4_to_f4(n_c);
        acc.x = fmaf(alpha, n.x + v.x, acc.x);
        acc.y = fmaf(alpha, n.y + v.y, acc.y);
        acc.z = fmaf(alpha, n.z + v.z, acc.z);
        acc.w = fmaf(alpha, n.w + v.w, acc.w);

        if (t < 75) {
            float4 w = h4_to_f4(w_c);
            accl.x = fmaf(alphal, w.x, accl.x);
            accl.y = fmaf(alphal, w.y, accl.y);
            accl.z = fmaf(alphal, w.z, accl.z);
            accl.w = fmaf(alphal, w.w, accl.w);
        }
        n_c = n_n;
        w_c = w_n;
    }

    // ---------- write fp16 ----------
    {
        size_t o = (size_t)d * 1024 + 4 * t;
        g_zf_h[o + 0] = __float2half_rn(acc.x);
        g_zf_h[o + 1] = __float2half_rn(acc.y);
        g_zf_h[o + 2] = __float2half_rn(acc.z);
        g_zf_h[o + 3] = __float2half_rn(acc.w);
    }
    if (t < 75) {
        size_t o = (size_t)d * 320 + 4 * t;
        g_zfl_h[o + 0] = __float2half_rn(accl.x);
        g_zfl_h[o + 1] = __float2half_rn(accl.y);
        g_zfl_h[o + 2] = __float2half_rn(accl.z);
        g_zfl_h[o + 3] = __float2half_rn(accl.w);
    }
}

// ================= launch =================
extern "C" void kernel_launch(void* const* d_in, const int* in_sizes, int n_in,
                              void* d_out, int out_size) {
    const float* n_f  = (const float*)d_in[0];
    const float* w2v  = (const float*)d_in[1];
    const float* s_f  = (const float*)d_in[2];
    const int*   src  = (const int*)d_in[3];
    const int*   dst  = (const int*)d_in[4];
    const float* We   = (const float*)d_in[5];
    const float* be   = (const float*)d_in[6];
    const float* Wel  = (const float*)d_in[7];
    const float* bel  = (const float*)d_in[8];
    const float* Wa   = (const float*)d_in[9];
    const float* Wal  = (const float*)d_in[11];
    const float* Wn   = (const float*)d_in[13];
    const float* bn   = (const float*)d_in[14];
    const float* Wnl  = (const float*)d_in[15];
    const float* bnl  = (const float*)d_in[16];

    float* out      = (float*)d_out;
    float* out_lang = out + (size_t)N_NODES * 1024;

    __half *P_h, *Q_h;
    __half *nf_h, *w2v_h, *zf_h, *zfl_h;
    __half *WeT_h, *WnT_h, *WelT_h, *WnlT_h;
    cudaGetSymbolAddress((void**)&P_h, g_P_h);
    cudaGetSymbolAddress((void**)&Q_h, g_Q_h);
    cudaGetSymbolAddress((void**)&nf_h, g_nf_h);
    cudaGetSymbolAddress((void**)&w2v_h, g_w2v_h);
    cudaGetSymbolAddress((void**)&zf_h, g_zf_h);
    cudaGetSymbolAddress((void**)&zfl_h, g_zfl_h);
    cudaGetSymbolAddress((void**)&WeT_h, g_WeT_h);
    cudaGetSymbolAddress((void**)&WnT_h, g_WnT_h);
    cudaGetSymbolAddress((void**)&WelT_h, g_WelT_h);
    cudaGetSymbolAddress((void**)&WnlT_h, g_WnlT_h);

    cudaFuncSetAttribute(mma_gemm, cudaFuncAttributeMaxDynamicSharedMemorySize, GEMM_SMEM);
    cudaFuncSetAttribute(combine_all, cudaFuncAttributeMaxDynamicSharedMemorySize,
                         CACHE_E * 1024 * sizeof(__half));

    dim3 tblk(32, 8);

    // launch order arranged so profiled launch #5 is the big P GEMM
    zero_cnt_kernel<<<8, 1024>>>();                                                   // 0
    round_rows2<<<2048, 256>>>(n_f, nf_h, w2v, w2v_h);                                // 1
    transpose_round2<<<dim3(32, 32, 2), tblk>>>(We, We + (size_t)1040 * 1024,
                                                1024, 1024, 1024, WeT_h, 1024,
                                                0, 1024);                             // 2
    hist_kernel<<<64, 1024>>>(dst);                                                   // 3
    scan_kernel<<<1, 1024>>>();                                                       // 4
    mma_gemm<<<dim3(16, 64), 256, GEMM_SMEM>>>(nullptr, P_h, 2048, 2048,
        nf_h, WeT_h, 1024, nullptr, nullptr, 0, nullptr, 0);                          // 5 (profiled)
    fill_kernel<<<64, 1024>>>(dst);                                                   // 6
    transpose_round2<<<dim3(19, 10, 2), tblk>>>(Wel, Wel + (size_t)300 * 600,
                                                600, 300, 600, WelT_h, 320,
                                                0, 600);                              // 7
    mma_gemm<<<dim3(10, 64), 256, GEMM_SMEM>>>(nullptr, Q_h, 1200, 1200,
        w2v_h, WelT_h, 320, nullptr, nullptr, 0, nullptr, 0);                         // 8
    transpose_round2<<<dim3(32, 32, 2), tblk>>>(Wn, Wn + (size_t)1024 * 1024,
                                                1024, 1024, 1024, WnT_h, 1024,
                                                0, 1024);                             // 9
    transpose_round2<<<dim3(10, 10, 2), tblk>>>(Wnl, Wnl + (size_t)300 * 300,
                                                300, 300, 300, WnlT_h, 320,
                                                0, 300);                              // 10

    combine_all<<<N_NODES, 256, CACHE_E * 1024 * sizeof(__half)>>>(
        n_f, w2v, s_f, src, We, be, Wa, bel, Wal);                                    // 11

    mma_gemm<<<dim3(8, 64), 256, GEMM_SMEM>>>(out, nullptr, 1024, 1024,
        nf_h, WnT_h, 1024,
        zf_h, WnT_h + (size_t)1024 * 1024, 1024,
        bn, 1);                                                                       // 12
    mma_gemm<<<dim3(3, 64), 256, GEMM_SMEM>>>(out_lang, nullptr, 300, 300,
        w2v_h, WnlT_h, 320,
        zfl_h, WnlT_h + (size_t)300 * 320, 320,
        bnl, 1);                                                                      // 13
}

// round 13
// speedup vs baseline: 1.2643x; 1.0654x over previous
#include <cuda_runtime.h>
#include <cuda_fp16.h>
#include <cstdint>
#include <cstddef>

#define N_NODES 8192
#define N_EDGES 65536
#define CACHE_E 16
#define MAXDEG 256

// ================= scratch (device globals) =================
__device__ __half g_P_h[(size_t)N_NODES * 2048];   // [P1 | P3]
__device__ __half g_Q_h[(size_t)N_NODES * 1200];   // [Q1 | Q2]

// CSR by dst
__device__ int g_cnt[N_NODES];
__device__ int g_off[N_NODES];
__device__ int g_fill[N_NODES];
__device__ int g_eid[N_EDGES];

// fp16 operands
__device__ __half g_nf_h[(size_t)N_NODES * 1024];
__device__ __half g_w2v_h[(size_t)N_NODES * 320];
__device__ __half g_zf_h[(size_t)N_NODES * 1024];
__device__ __half g_zfl_h[(size_t)N_NODES * 320];
__device__ __half g_WeT_h[(size_t)2048 * 1024];
__device__ __half g_WnT_h[(size_t)2048 * 1024];
__device__ __half g_WelT_h[(size_t)1280 * 320];
__device__ __half g_WnlT_h[(size_t)768 * 320];

// ================= small helpers =================
__device__ __forceinline__ uint32_t smem_u32(const void* p) {
    uint32_t a;
    asm("{ .reg .u64 t; cvta.to.shared.u64 t, %1; cvt.u32.u64 %0, t; }" : "=r"(a) : "l"(p));
    return a;
}
__device__ __forceinline__ void cp16(uint32_t dst, const void* src) {
    asm volatile("cp.async.cg.shared.global [%0], [%1], 16;" :: "r"(dst), "l"(src) : "memory");
}
__device__ __forceinline__ void cp8(uint32_t dst, const void* src) {
    asm volatile("cp.async.ca.shared.global [%0], [%1], 8;" :: "r"(dst), "l"(src) : "memory");
}
__device__ __forceinline__ void cp_commit() {
    asm volatile("cp.async.commit_group;" ::: "memory");
}
__device__ __forceinline__ void cp_wait_all() {
    asm volatile("cp.async.wait_group 0;" ::: "memory");
}
__device__ __forceinline__ void ldmx4(uint32_t* r, uint32_t addr) {
    asm volatile("ldmatrix.sync.aligned.m8n8.x4.shared.b16 {%0,%1,%2,%3}, [%4];"
                 : "=r"(r[0]), "=r"(r[1]), "=r"(r[2]), "=r"(r[3]) : "r"(addr));
}
__device__ __forceinline__ void mma_f16(float* c, const uint32_t* a, const uint32_t* b) {
    asm volatile(
        "mma.sync.aligned.m16n8k16.row.col.f32.f16.f16.f32 "
        "{%0,%1,%2,%3}, {%4,%5,%6,%7}, {%8,%9}, {%0,%1,%2,%3};"
        : "+f"(c[0]), "+f"(c[1]), "+f"(c[2]), "+f"(c[3])
        : "r"(a[0]), "r"(a[1]), "r"(a[2]), "r"(a[3]), "r"(b[0]), "r"(b[1]));
}
__device__ __forceinline__ float4 h4_to_f4(uint2 pk) {
    __half2 h0 = *(__half2*)&pk.x;
    __half2 h1 = *(__half2*)&pk.y;
    float2 f0 = __half22float2(h0);
    float2 f1 = __half22float2(h1);
    return make_float4(f0.x, f0.y, f1.x, f1.y);
}

// ================= batched fp16 HMMA GEMM =================
#define KC 64
#define TILE_B 16384
#define STAGE_B (2 * TILE_B)
#define GEMM_SMEM (2 * STAGE_B)

struct GemmJob {
    float* C; __half* Ch; int ldc; int Nvalid;
    const __half* A1; const __half* B1; int K1;
    const __half* A2; const __half* B2; int K2;
    const float* bias; int do_relu; int bx;
};

__device__ __forceinline__ void issue_chunk(
    uint32_t sb_stage,
    const __half* A, const __half* B,
    int ldA, int ldB, int rowBase, int colBase, int k0, int tid)
{
#pragma unroll
    for (int t = 0; t < 2; ++t) {
        const __half* src = (t == 0) ? A : B;
        const int row0 = (t == 0) ? rowBase : colBase;
        const int ld = (t == 0) ? ldA : ldB;
        const uint32_t tb = sb_stage + t * TILE_B;
#pragma unroll
        for (int i = 0; i < 4; ++i) {
            int idx = i * 256 + tid;
            int r = idx >> 3;
            int cch = idx & 7;
            uint32_t dst = tb + r * 128 + (((cch ^ (r & 7))) << 4);
            cp16(dst, src + (size_t)(row0 + r) * ld + k0 + cch * 8);
        }
    }
}

__global__ __launch_bounds__(256, 2) void mma_gemm(GemmJob j0, GemmJob j1)
{
    const GemmJob j = (blockIdx.z == 0) ? j0 : j1;
    if ((int)blockIdx.x >= j.bx) return;

    extern __shared__ char smem[];
    const uint32_t sb = smem_u32(smem);
    const int tid = threadIdx.x;
    const int wid = tid >> 5;
    const int lane = tid & 31;
    const int warp_m = wid & 3;
    const int warp_n = wid >> 2;
    const int rowBase = blockIdx.y * 128;
    const int colBase = blockIdx.x * 128;

    float c[2][8][4];
#pragma unroll
    for (int i = 0; i < 2; ++i)
#pragma unroll
        for (int jn = 0; jn < 8; ++jn)
#pragma unroll
            for (int k = 0; k < 4; ++k) c[i][jn][k] = 0.f;

    const int NC1 = j.K1 / KC;
    const int NC2 = j.K2 / KC;
    const int NC = NC1 + NC2;

    issue_chunk(sb, j.A1, j.B1, j.K1, j.K1, rowBase, colBase, 0, tid);
    cp_commit();

#pragma unroll 1
    for (int ch = 0; ch < NC; ++ch) {
        const uint32_t cur = sb + (uint32_t)(ch & 1) * STAGE_B;
        if (ch + 1 < NC) {
            int nc = ch + 1;
            if (nc < NC1)
                issue_chunk(sb + (uint32_t)(nc & 1) * STAGE_B, j.A1, j.B1,
                            j.K1, j.K1, rowBase, colBase, nc * KC, tid);
            else
                issue_chunk(sb + (uint32_t)(nc & 1) * STAGE_B, j.A2, j.B2,
                            j.K2, j.K2, rowBase, colBase, (nc - NC1) * KC, tid);
            cp_commit();
            asm volatile("cp.async.wait_group 1;" ::: "memory");
        } else {
            cp_wait_all();
        }
        __syncthreads();

#pragma unroll
        for (int ks = 0; ks < 4; ++ks) {
            uint32_t ah[2][4], bh[4][4];
#pragma unroll
            for (int mf = 0; mf < 2; ++mf) {
                int row = warp_m * 32 + mf * 16 + ((lane >> 3) & 1) * 8 + (lane & 7);
                int chunk = ks * 2 + (lane >> 4);
                uint32_t ad = cur + row * 128 + ((chunk ^ (row & 7)) << 4);
                ldmx4(ah[mf], ad);
            }
#pragma unroll
            for (int nf2 = 0; nf2 < 4; ++nf2) {
                int row = warp_n * 64 + nf2 * 16 + (lane >> 4) * 8 + (lane & 7);
                int chunk = ks * 2 + ((lane >> 3) & 1);
                uint32_t bd = cur + TILE_B + row * 128 + ((chunk ^ (row & 7)) << 4);
                ldmx4(bh[nf2], bd);
            }
#pragma unroll
            for (int mf = 0; mf < 2; ++mf)
#pragma unroll
                for (int nf = 0; nf < 8; ++nf)
                    mma_f16(c[mf][nf], ah[mf], &bh[nf >> 1][(nf & 1) * 2]);
        }
        __syncthreads();
    }

    const int r0 = rowBase + warp_m * 32 + (lane >> 2);
    const int colb = colBase + warp_n * 64 + (lane & 3) * 2;
#pragma unroll
    for (int mf = 0; mf < 2; ++mf) {
        int row = r0 + mf * 16;
#pragma unroll
        for (int nf = 0; nf < 8; ++nf) {
            int col = colb + nf * 8;
            if (col < j.Nvalid) {
                float b0 = 0.f, b1 = 0.f;
                if (j.bias) { b0 = j.bias[col]; b1 = j.bias[col + 1]; }
                float2 v0, v1;
                v0.x = c[mf][nf][0] + b0; v0.y = c[mf][nf][1] + b1;
                v1.x = c[mf][nf][2] + b0; v1.y = c[mf][nf][3] + b1;
                if (j.do_relu) {
                    v0.x = fmaxf(v0.x, 0.f); v0.y = fmaxf(v0.y, 0.f);
                    v1.x = fmaxf(v1.x, 0.f); v1.y = fmaxf(v1.y, 0.f);
                }
                if (j.Ch) {
                    __half2 h0 = __floats2half2_rn(v0.x, v0.y);
                    __half2 h1 = __floats2half2_rn(v1.x, v1.y);
                    *(__half2*)(j.Ch + (size_t)row * j.ldc + col) = h0;
                    *(__half2*)(j.Ch + (size_t)(row + 8) * j.ldc + col) = h1;
                } else {
                    *(float2*)(j.C + (size_t)row * j.ldc + col) = v0;
                    *(float2*)(j.C + (size_t)(row + 8) * j.ldc + col) = v1;
                }
            }
        }
    }
}

// ================= conversion kernels (merged) =================
__global__ void round_rows2(const float* __restrict__ a, __half* __restrict__ ah,
                            const float* __restrict__ b, __half* __restrict__ bh) {
    const size_t T1 = (size_t)N_NODES * 1024;
    const size_t T2 = (size_t)N_NODES * 320;
    size_t stride = (size_t)gridDim.x * blockDim.x;
    for (size_t i = (size_t)blockIdx.x * blockDim.x + threadIdx.x; i < T1 + T2; i += stride) {
        if (i < T1) {
            ah[i] = __float2half_rn(a[i]);
        } else {
            size_t jj = i - T1;
            int row = (int)(jj / 320);
            int col = (int)(jj % 320);
            float v = (col < 300) ? b[(size_t)row * 300 + col] : 0.f;
            bh[jj] = __float2half_rn(v);
        }
    }
}

__global__ void transpose_round2(const float* __restrict__ W0, const float* __restrict__ W1,
                                 int ldw, int K, int N,
                                 __half* __restrict__ hi, int Kd, int n0_0, int n0_1) {
    const float* W = blockIdx.z ? W1 : W0;
    const int n0 = blockIdx.z ? n0_1 : n0_0;
    __shared__ float tile[32][33];
    int kb = blockIdx.y * 32, nb = blockIdx.x * 32;
#pragma unroll
    for (int i = 0; i < 4; ++i) {
        int k = kb + threadIdx.y + i * 8;
        int n = nb + threadIdx.x;
        tile[threadIdx.y + i * 8][threadIdx.x] = (k < K && n < N) ? W[(size_t)k * ldw + n] : 0.f;
    }
    __syncthreads();
#pragma unroll
    for (int i = 0; i < 4; ++i) {
        int n = nb + threadIdx.y + i * 8;
        int k = kb + threadIdx.x;
        if (n < N && k < Kd)
            hi[(size_t)(n0 + n) * Kd + k] = __float2half_rn(tile[threadIdx.x][threadIdx.y + i * 8]);
    }
}

// ================= CSR construction =================
__global__ void zero_cnt_kernel() {
    int i = blockIdx.x * blockDim.x + threadIdx.x;
    if (i < N_NODES) g_cnt[i] = 0;
}
__global__ void hist_kernel(const int* __restrict__ dst) {
    int e = blockIdx.x * blockDim.x + threadIdx.x;
    if (e < N_EDGES) atomicAdd(&g_cnt[dst[e]], 1);
}
__global__ __launch_bounds__(1024) void scan_kernel() {
    __shared__ int sm[1024];
    int t = threadIdx.x;
    int loc[8];
    int s = 0;
#pragma unroll
    for (int i = 0; i < 8; ++i) { loc[i] = g_cnt[t * 8 + i]; s += loc[i]; }
    sm[t] = s;
    __syncthreads();
    for (int off = 1; off < 1024; off <<= 1) {
        int v = sm[t];
        if (t >= off) v += sm[t - off];
        __syncthreads();
        sm[t] = v;
        __syncthreads();
    }
    int run = (t == 0) ? 0 : sm[t - 1];
#pragma unroll
    for (int i = 0; i < 8; ++i) {
        g_off[t * 8 + i] = run;
        g_fill[t * 8 + i] = run;
        run += loc[i];
    }
}
__global__ void fill_kernel(const int* __restrict__ dst) {
    int e = blockIdx.x * blockDim.x + threadIdx.x;
    if (e < N_EDGES) {
        int pos = atomicAdd(&g_fill[dst[e]], 1);
        g_eid[pos] = e;
    }
}

// ================= merged score+softmax+combine kernel =================
// dynamic smem: efc (CACHE_E*1024h) | nfc (CACHE_E*1024h) | wvc (CACHE_E*320h)
#define COMB_SMEM ((2 * CACHE_E * 1024 + CACHE_E * 320) * 2)

__global__ __launch_bounds__(256) void combine_all(
    const float* __restrict__ n_f, const float* __restrict__ w2v,
    const float* __restrict__ s_f, const int* __restrict__ src,
    const float* __restrict__ We, const float* __restrict__ be,
    const float* __restrict__ Wa,
    const float* __restrict__ bel, const float* __restrict__ Wal)
{
    extern __shared__ __half dyn[];
    __half* efc = dyn;
    __half* nfc = dyn + CACHE_E * 1024;
    __half* wvc = dyn + 2 * CACHE_E * 1024;
    const uint32_t efc_b = smem_u32(efc);
    const uint32_t nfc_b = smem_u32(nfc);
    const uint32_t wvc_b = smem_u32(wvc);

    const int d = blockIdx.x;
    const int t = threadIdx.x;
    const int lane = t & 31;
    const int deg = g_cnt[d];
    const int start = g_off[d];
    const int cdeg = (deg < CACHE_E) ? deg : CACHE_E;

    __shared__ int sm_eid[MAXDEG], sm_src[MAXDEG];
    __shared__ float sm_af[MAXDEG], sm_afl[MAXDEG];
    __shared__ float sm_scal[4];

    for (int i = t; i < deg; i += 256) {
        int e = g_eid[start + i];
        sm_eid[i] = e;
        sm_src[i] = src[e];
    }
    for (int i = t; i < MAXDEG; i += 256) { sm_af[i] = 0.f; sm_afl[i] = 0.f; }
    __syncthreads();

    // ---------- Phase A0: bulk-gather P rows (full MLP) ----------
#pragma unroll 1
    for (int i = 0; i < cdeg; ++i)
        cp8(efc_b + (uint32_t)(i * 1024 + 4 * t) * 2,
            g_P_h + (size_t)sm_src[i] * 2048 + 4 * t);
    cp_commit();

    // per-block preloads (overlap with the async gathers)
    const float4* Ws4 = (const float4*)(We + (size_t)1024 * 1024);
    float4 wsr[16];
#pragma unroll
    for (int k = 0; k < 16; ++k) wsr[k] = Ws4[k * 256 + t];

    float4 p3r;
    {
        uint2 pr = *(const uint2*)(g_P_h + (size_t)d * 2048 + 1024 + 4 * t);
        p3r = h4_to_f4(pr);
        float4 ber = ((const float4*)be)[t];
        p3r.x += ber.x; p3r.y += ber.y; p3r.z += ber.z; p3r.w += ber.w;
    }
    float4 war = ((const float4*)Wa)[t];
    float4 q2r = make_float4(0.f, 0.f, 0.f, 0.f);
    float4 walr = make_float4(0.f, 0.f, 0.f, 0.f);
    if (t < 150) {
        uint2 qr = *(const uint2*)(g_Q_h + (size_t)d * 1200 + 600 + 4 * t);
        q2r = h4_to_f4(qr);
        float4 belr = ((const float4*)bel)[t];
        q2r.x += belr.x; q2r.y += belr.y; q2r.z += belr.z; q2r.w += belr.w;
        walr = ((const float4*)Wal)[t];
    }

    cp_wait_all();
    __syncthreads();

    // ---------- Phase A: e_f + scores ----------
    uint2 qr_c = make_uint2(0u, 0u);
    if (deg > 0 && t < 150)
        qr_c = *(const uint2*)(g_Q_h + (size_t)sm_src[0] * 1200 + 4 * t);

#pragma unroll 1
    for (int i = 0; i < deg; ++i) {
        const int eid = sm_eid[i];

        const float4* sf4 = (const float4*)(s_f + (size_t)eid * 16);
        float4 sv0 = __ldg(sf4 + 0), sv1 = __ldg(sf4 + 1);
        float4 sv2 = __ldg(sf4 + 2), sv3 = __ldg(sf4 + 3);

        uint2 qr_n = make_uint2(0u, 0u);
        if (i + 1 < deg && t < 150)
            qr_n = *(const uint2*)(g_Q_h + (size_t)sm_src[i + 1] * 1200 + 4 * t);

        uint2 pr;
        if (i < CACHE_E)
            pr = *(const uint2*)(efc + i * 1024 + 4 * t);
        else
            pr = *(const uint2*)(g_P_h + (size_t)sm_src[i] * 2048 + 4 * t);

        float4 v = h4_to_f4(pr);
        v.x += p3r.x; v.y += p3r.y; v.z += p3r.z; v.w += p3r.w;
        float sfs[16] = {sv0.x, sv0.y, sv0.z, sv0.w, sv1.x, sv1.y, sv1.z, sv1.w,
                         sv2.x, sv2.y, sv2.z, sv2.w, sv3.x, sv3.y, sv3.z, sv3.w};
#pragma unroll
        for (int k = 0; k < 16; ++k) {
            v.x = fmaf(sfs[k], wsr[k].x, v.x); v.y = fmaf(sfs[k], wsr[k].y, v.y);
            v.z = fmaf(sfs[k], wsr[k].z, v.z); v.w = fmaf(sfs[k], wsr[k].w, v.w);
        }
        v.x = fmaxf(v.x, 0.f); v.y = fmaxf(v.y, 0.f);
        v.z = fmaxf(v.z, 0.f); v.w = fmaxf(v.w, 0.f);
        if (i < CACHE_E) {
            __half2 h0 = __floats2half2_rn(v.x, v.y);
            __half2 h1 = __floats2half2_rn(v.z, v.w);
            uint2 pk;
            pk.x = *(uint32_t*)&h0;
            pk.y = *(uint32_t*)&h1;
            *(uint2*)(efc + i * 1024 + 4 * t) = pk;   // overwrite P row with e_f
        }

        float acc = v.x * war.x + v.y * war.y + v.z * war.z + v.w * war.w;

        float accl = 0.f;
        if (t < 150) {
            float4 u = h4_to_f4(qr_c);
            u.x += q2r.x; u.y += q2r.y; u.z += q2r.z; u.w += q2r.w;
            u.x = fmaxf(u.x, 0.f); u.y = fmaxf(u.y, 0.f);
            u.z = fmaxf(u.z, 0.f); u.w = fmaxf(u.w, 0.f);
            accl = u.x * walr.x + u.y * walr.y + u.z * walr.z + u.w * walr.w;
        }

#pragma unroll
        for (int off = 16; off > 0; off >>= 1) {
            acc += __shfl_down_sync(0xffffffffu, acc, off);
            accl += __shfl_down_sync(0xffffffffu, accl, off);
        }
        if (lane == 0) {
            atomicAdd(&sm_af[i], acc);
            if (accl != 0.f) atomicAdd(&sm_afl[i], accl);
        }
        qr_c = qr_n;
    }

    // ---------- Phase B0: bulk-gather nf / w2v rows (overlaps softmax) ----------
#pragma unroll 1
    for (int i = 0; i < cdeg; ++i) {
        int s = sm_src[i];
        cp8(nfc_b + (uint32_t)(i * 1024 + 4 * t) * 2,
            g_nf_h + (size_t)s * 1024 + 4 * t);
        if (t < 75)
            cp8(wvc_b + (uint32_t)(i * 320 + 4 * t) * 2,
                g_w2v_h + (size_t)s * 320 + 4 * t);
    }
    cp_commit();
    __syncthreads();   // sm_af/sm_afl complete

    // ---------- softmax scalars (warp 0) ----------
    if (t < 32) {
        float m = -1e30f, ml = -1e30f;
        for (int i = t; i < deg; i += 32) {
            m = fmaxf(m, sm_af[i]);
            ml = fmaxf(ml, sm_afl[i]);
        }
#pragma unroll
        for (int off = 16; off > 0; off >>= 1) {
            m = fmaxf(m, __shfl_xor_sync(0xffffffffu, m, off));
            ml = fmaxf(ml, __shfl_xor_sync(0xffffffffu, ml, off));
        }
        float den = 0.f, denl = 0.f;
        for (int i = t; i < deg; i += 32) {
            den += expf(sm_af[i] - m);
            denl += expf(sm_afl[i] - ml);
        }
#pragma unroll
        for (int off = 16; off > 0; off >>= 1) {
            den += __shfl_xor_sync(0xffffffffu, den, off);
            denl += __shfl_xor_sync(0xffffffffu, denl, off);
        }
        if (t == 0) {
            sm_scal[0] = m;
            sm_scal[1] = (deg > 0) ? 1.f / den : 0.f;
            sm_scal[2] = ml;
            sm_scal[3] = (deg > 0) ? 1.f / denl : 0.f;
        }
    }
    __syncthreads();

    {
        const float m = sm_scal[0], rden = sm_scal[1];
        const float ml = sm_scal[2], rdenl = sm_scal[3];
        for (int i = t; i < deg; i += 256) {
            sm_af[i] = expf(sm_af[i] - m) * rden;
            sm_afl[i] = expf(sm_afl[i] - ml) * rdenl;
        }
    }
    cp_wait_all();
    __syncthreads();

    // ---------- Phase B: weighted accumulate (smem-resident) ----------
    float4 acc = make_float4(0.f, 0.f, 0.f, 0.f);
    float4 accl = make_float4(0.f, 0.f, 0.f, 0.f);

#pragma unroll 1
    for (int i = 0; i < deg; ++i) {
        const float alpha = sm_af[i];
        const float alphal = sm_afl[i];

        float4 v, n;
        if (i < CACHE_E) {
            v = h4_to_f4(*(const uint2*)(efc + i * 1024 + 4 * t));
            n = h4_to_f4(*(const uint2*)(nfc + i * 1024 + 4 * t));
        } else {
            const int s = sm_src[i];
            const int eid = sm_eid[i];
            uint2 pr = *(const uint2*)(g_P_h + (size_t)s * 2048 + 4 * t);
            v = h4_to_f4(pr);
            v.x += p3r.x; v.y += p3r.y; v.z += p3r.z; v.w += p3r.w;
            const float4* sf4 = (const float4*)(s_f + (size_t)eid * 16);
            float4 sv0 = __ldg(sf4 + 0), sv1 = __ldg(sf4 + 1);
            float4 sv2 = __ldg(sf4 + 2), sv3 = __ldg(sf4 + 3);
            float sfs[16] = {sv0.x, sv0.y, sv0.z, sv0.w, sv1.x, sv1.y, sv1.z, sv1.w,
                             sv2.x, sv2.y, sv2.z, sv2.w, sv3.x, sv3.y, sv3.z, sv3.w};
#pragma unroll
            for (int k = 0; k < 16; ++k) {
                v.x = fmaf(sfs[k], wsr[k].x, v.x); v.y = fmaf(sfs[k], wsr[k].y, v.y);
                v.z = fmaf(sfs[k], wsr[k].z, v.z); v.w = fmaf(sfs[k], wsr[k].w, v.w);
            }
            v.x = fmaxf(v.x, 0.f); v.y = fmaxf(v.y, 0.f);
            v.z = fmaxf(v.z, 0.f); v.w = fmaxf(v.w, 0.f);
            n = h4_to_f4(*(const uint2*)(g_nf_h + (size_t)s * 1024 + 4 * t));
        }

        acc.x = fmaf(alpha, n.x + v.x, acc.x);
        acc.y = fmaf(alpha, n.y + v.y, acc.y);
        acc.z = fmaf(alpha, n.z + v.z, acc.z);
        acc.w = fmaf(alpha, n.w + v.w, acc.w);

        if (t < 75) {
            float4 w;
            if (i < CACHE_E)
                w = h4_to_f4(*(const uint2*)(wvc + i * 320 + 4 * t));
            else
                w = h4_to_f4(*(const uint2*)(g_w2v_h + (size_t)sm_src[i] * 320 + 4 * t));
            accl.x = fmaf(alphal, w.x, accl.x);
            accl.y = fmaf(alphal, w.y, accl.y);
            accl.z = fmaf(alphal, w.z, accl.z);
            accl.w = fmaf(alphal, w.w, accl.w);
        }
    }

    // ---------- write fp16 ----------
    {
        size_t o = (size_t)d * 1024 + 4 * t;
        g_zf_h[o + 0] = __float2half_rn(acc.x);
        g_zf_h[o + 1] = __float2half_rn(acc.y);
        g_zf_h[o + 2] = __float2half_rn(acc.z);
        g_zf_h[o + 3] = __float2half_rn(acc.w);
    }
    if (t < 75) {
        size_t o = (size_t)d * 320 + 4 * t;
        g_zfl_h[o + 0] = __float2half_rn(accl.x);
        g_zfl_h[o + 1] = __float2half_rn(accl.y);
        g_zfl_h[o + 2] = __float2half_rn(accl.z);
        g_zfl_h[o + 3] = __float2half_rn(accl.w);
    }
}

// ================= launch =================
extern "C" void kernel_launch(void* const* d_in, const int* in_sizes, int n_in,
                              void* d_out, int out_size) {
    const float* n_f  = (const float*)d_in[0];
    const float* w2v  = (const float*)d_in[1];
    const float* s_f  = (const float*)d_in[2];
    const int*   src  = (const int*)d_in[3];
    const int*   dst  = (const int*)d_in[4];
    const float* We   = (const float*)d_in[5];
    const float* be   = (const float*)d_in[6];
    const float* Wel  = (const float*)d_in[7];
    const float* bel  = (const float*)d_in[8];
    const float* Wa   = (const float*)d_in[9];
    const float* Wal  = (const float*)d_in[11];
    const float* Wn   = (const float*)d_in[13];
    const float* bn   = (const float*)d_in[14];
    const float* Wnl  = (const float*)d_in[15];
    const float* bnl  = (const float*)d_in[16];

    float* out      = (float*)d_out;
    float* out_lang = out + (size_t)N_NODES * 1024;

    __half *P_h, *Q_h;
    __half *nf_h, *w2v_h, *zf_h, *zfl_h;
    __half *WeT_h, *WnT_h, *WelT_h, *WnlT_h;
    cudaGetSymbolAddress((void**)&P_h, g_P_h);
    cudaGetSymbolAddress((void**)&Q_h, g_Q_h);
    cudaGetSymbolAddress((void**)&nf_h, g_nf_h);
    cudaGetSymbolAddress((void**)&w2v_h, g_w2v_h);
    cudaGetSymbolAddress((void**)&zf_h, g_zf_h);
    cudaGetSymbolAddress((void**)&zfl_h, g_zfl_h);
    cudaGetSymbolAddress((void**)&WeT_h, g_WeT_h);
    cudaGetSymbolAddress((void**)&WnT_h, g_WnT_h);
    cudaGetSymbolAddress((void**)&WelT_h, g_WelT_h);
    cudaGetSymbolAddress((void**)&WnlT_h, g_WnlT_h);

    cudaFuncSetAttribute(mma_gemm, cudaFuncAttributeMaxDynamicSharedMemorySize, GEMM_SMEM);
    cudaFuncSetAttribute(combine_all, cudaFuncAttributeMaxDynamicSharedMemorySize, COMB_SMEM);

    dim3 tblk(32, 8);

    zero_cnt_kernel<<<8, 1024>>>();
    round_rows2<<<2048, 256>>>(n_f, nf_h, w2v, w2v_h);
    transpose_round2<<<dim3(32, 32, 2), tblk>>>(We, We + (size_t)1040 * 1024,
                                                1024, 1024, 1024, WeT_h, 1024, 0, 1024);
    transpose_round2<<<dim3(19, 10, 2), tblk>>>(Wel, Wel + (size_t)300 * 600,
                                                600, 300, 600, WelT_h, 320, 0, 600);
    hist_kernel<<<64, 1024>>>(dst);
    scan_kernel<<<1, 1024>>>();
    fill_kernel<<<64, 1024>>>(dst);

    // batched projections: z=0 -> P, z=1 -> Q
    {
        GemmJob jp = {nullptr, P_h, 2048, 2048, nf_h, WeT_h, 1024,
                      nullptr, nullptr, 0, nullptr, 0, 16};
        GemmJob jq = {nullptr, Q_h, 1200, 1200, w2v_h, WelT_h, 320,
                      nullptr, nullptr, 0, nullptr, 0, 10};
        mma_gemm<<<dim3(16, 64, 2), 256, GEMM_SMEM>>>(jp, jq);
    }

    transpose_round2<<<dim3(32, 32, 2), tblk>>>(Wn, Wn + (size_t)1024 * 1024,
                                                1024, 1024, 1024, WnT_h, 1024, 0, 1024);
    transpose_round2<<<dim3(10, 10, 2), tblk>>>(Wnl, Wnl + (size_t)300 * 300,
                                                300, 300, 300, WnlT_h, 320, 0, 300);

    combine_all<<<N_NODES, 256, COMB_SMEM>>>(
        n_f, w2v, s_f, src, We, be, Wa, bel, Wal);

    // batched node-apply: z=0 -> out, z=1 -> out_lang
    {
        GemmJob jo = {out, nullptr, 1024, 1024, nf_h, WnT_h, 1024,
                      zf_h, WnT_h + (size_t)1024 * 1024, 1024, bn, 1, 8};
        GemmJob jl = {out_lang, nullptr, 300, 300, w2v_h, WnlT_h, 320,
                      zfl_h, WnlT_h + (size_t)300 * 320, 320, bnl, 1, 3};
        mma_gemm<<<dim3(8, 64, 2), 256, GEMM_SMEM>>>(jo, jl);
    }
}